// round 13
// baseline (speedup 1.0000x reference)
#include <cuda_runtime.h>
#include <cuda_bf16.h>
#include <math.h>

// Problem constants
#define BSZ 4
#define SEQ 2048
#define DIM 512
#define NHEAD 8
#define NLAYER 4
#define FFDIM 2048
#define HDIM 64
#define HALFHD 32
#define EPSV 1e-6f
#define ALPHAV 0.5f
#define LOG_ROPE_BASE 9.210340371976184   // ln(10000)

#define BT (BSZ * SEQ)                    // 8192

typedef unsigned int u32;
typedef unsigned long long u64;
typedef __nv_bfloat16 bf16;

// ---------------- scratch buffers ----------------
constexpr size_t NX    = (size_t)BT * DIM;
constexpr size_t NHID  = (size_t)BT * FFDIM;
constexpr size_t NSEGS = (size_t)BSZ * (SEQ + 1) * DIM;
constexpr size_t NSEGC = (size_t)BSZ * (SEQ + 1);
constexpr size_t NROPE = (size_t)SEQ * HALFHD;

constexpr size_t OFF_X    = 0;
constexpr size_t OFF_Y    = OFF_X  + NX;
constexpr size_t OFF_Q    = OFF_Y  + NX;   // qr,kr,vr contiguous (fused QKV)
constexpr size_t OFF_K    = OFF_Q  + NX;
constexpr size_t OFF_V    = OFF_K  + NX;
constexpr size_t OFF_HF   = OFF_V  + NX;
constexpr size_t OFF_SSUM = OFF_HF + NX;
constexpr size_t OFF_SCNT = OFF_SSUM + NSEGS;
constexpr size_t OFF_COS  = OFF_SCNT + NSEGC;
constexpr size_t OFF_SIN  = OFF_COS + NROPE;
constexpr size_t TOTALF   = OFF_SIN + NROPE;

__device__ float g_buf[TOTALF];
__device__ int   g_seg[BT];

// bf16 activation planes (hi plane, then lo plane at +delta)
constexpr size_t BXN = 0;
constexpr size_t BOC = 2 * NX;
constexpr size_t BQP = 4 * NX;
constexpr size_t BKP = 6 * NX;
constexpr size_t BVT = 8 * NX;
constexpr size_t BGG = 10 * NX;
constexpr size_t TOTALB = 10 * NX + 2 * NHID;
__device__ bf16 g_abuf[TOTALB];

// bf16 split weights
constexpr size_t NPROJ = (size_t)NLAYER * DIM * DIM;
constexpr size_t NFF   = (size_t)NLAYER * FFDIM * DIM;
constexpr size_t WQO = 0;
constexpr size_t WKO = 2 * NPROJ;
constexpr size_t WVO = 4 * NPROJ;
constexpr size_t WOO = 6 * NPROJ;
constexpr size_t W1O = 8 * NPROJ;
constexpr size_t W3O = W1O + 2 * NFF;
constexpr size_t W2O = W3O + 2 * NFF;
constexpr size_t TOTALW = W2O + 2 * NFF;
__device__ bf16 g_wsplit[TOTALW];

// ---------------- PTX helpers ----------------
__device__ __forceinline__ u32 smem_u32(const void* p) {
    u32 a;
    asm("{ .reg .u64 t; cvta.to.shared.u64 t, %1; cvt.u32.u64 %0, t; }" : "=r"(a) : "l"(p));
    return a;
}
__device__ __forceinline__ void ldsm4(u32 addr, u32& r0, u32& r1, u32& r2, u32& r3) {
    asm volatile("ldmatrix.sync.aligned.m8n8.x4.shared.b16 {%0,%1,%2,%3}, [%4];"
                 : "=r"(r0), "=r"(r1), "=r"(r2), "=r"(r3) : "r"(addr));
}
__device__ __forceinline__ void ldsm2(u32 addr, u32& r0, u32& r1) {
    asm volatile("ldmatrix.sync.aligned.m8n8.x2.shared.b16 {%0,%1}, [%2];"
                 : "=r"(r0), "=r"(r1) : "r"(addr));
}
__device__ __forceinline__ void mma16816(float* d, u32 a0, u32 a1, u32 a2, u32 a3,
                                         u32 b0, u32 b1) {
    asm volatile(
        "mma.sync.aligned.m16n8k16.row.col.f32.bf16.bf16.f32 "
        "{%0,%1,%2,%3}, {%4,%5,%6,%7}, {%8,%9}, {%0,%1,%2,%3};"
        : "+f"(d[0]), "+f"(d[1]), "+f"(d[2]), "+f"(d[3])
        : "r"(a0), "r"(a1), "r"(a2), "r"(a3), "r"(b0), "r"(b1));
}
__device__ __forceinline__ void cp16(u32 dst, const void* src) {
    asm volatile("cp.async.cg.shared.global [%0], [%1], 16;" :: "r"(dst), "l"(src));
}
__device__ __forceinline__ void cp_commit() { asm volatile("cp.async.commit_group;"); }
__device__ __forceinline__ void cp_wait0()  { asm volatile("cp.async.wait_group 0;" ::: "memory"); }
__device__ __forceinline__ void cp_wait1()  { asm volatile("cp.async.wait_group 1;" ::: "memory"); }

__device__ __forceinline__ void split_pack(float4 v, uint2& hp, uint2& lp) {
    __nv_bfloat162 h01, h23, l01, l23;
    h01.x = __float2bfloat16_rn(v.x);
    h01.y = __float2bfloat16_rn(v.y);
    h23.x = __float2bfloat16_rn(v.z);
    h23.y = __float2bfloat16_rn(v.w);
    l01.x = __float2bfloat16_rn(v.x - __bfloat162float(h01.x));
    l01.y = __float2bfloat16_rn(v.y - __bfloat162float(h01.y));
    l23.x = __float2bfloat16_rn(v.z - __bfloat162float(h23.x));
    l23.y = __float2bfloat16_rn(v.w - __bfloat162float(h23.y));
    hp.x = *reinterpret_cast<u32*>(&h01);
    hp.y = *reinterpret_cast<u32*>(&h23);
    lp.x = *reinterpret_cast<u32*>(&l01);
    lp.y = *reinterpret_cast<u32*>(&l23);
}
__device__ __forceinline__ void split2(float x, float y, u32& hi, u32& lo) {
    __nv_bfloat162 h, l;
    h.x = __float2bfloat16_rn(x);
    h.y = __float2bfloat16_rn(y);
    l.x = __float2bfloat16_rn(x - __bfloat162float(h.x));
    l.y = __float2bfloat16_rn(y - __bfloat162float(h.y));
    hi = *reinterpret_cast<u32*>(&h);
    lo = *reinterpret_cast<u32*>(&l);
}

__device__ __forceinline__ bool is_sep(int c) {
    switch (c) {
        case 9: case 10: case 13: case 32: case 33: case 34: case 35: case 36:
        case 37: case 38: case 39: case 40: case 41: case 42: case 43: case 44:
        case 45: case 46: case 47: case 58: case 59: case 60: case 61: case 62:
        case 63: case 64: case 91: case 92: case 93: case 94: case 123:
        case 124: case 125: case 126:
            return true;
        default:
            return false;
    }
}

// ---------------- small kernels ----------------
struct WSrc { const float* s[7]; };
constexpr size_t P4 = NPROJ / 4;
constexpr size_t F4 = NFF / 4;
constexpr size_t TOT4 = 4 * P4 + 3 * F4;

__global__ void wsplit_all_kernel(WSrc src, bf16* __restrict__ ws) {
    size_t i4 = (size_t)blockIdx.x * blockDim.x + threadIdx.x;
    if (i4 >= TOT4) return;
    int r;
    size_t local;
    bf16 *hi, *lo;
    const float* s;
    if (i4 < 4 * P4) {
        r = (int)(i4 / P4);
        local = i4 - (size_t)r * P4;
        s = src.s[r];
        hi = ws + (size_t)r * 2 * NPROJ;
        lo = hi + NPROJ;
    } else {
        size_t j = i4 - 4 * P4;
        r = (int)(j / F4);
        local = j - (size_t)r * F4;
        s = src.s[4 + r];
        hi = ws + W1O + (size_t)r * 2 * NFF;
        lo = hi + NFF;
    }
    float4 v = reinterpret_cast<const float4*>(s)[local];
    uint2 hp, lp;
    split_pack(v, hp, lp);
    *reinterpret_cast<uint2*>(hi + local * 4) = hp;
    *reinterpret_cast<uint2*>(lo + local * 4) = lp;
}

__global__ void embed_kernel(const int* __restrict__ tokens,
                             const float* __restrict__ embed,
                             float* __restrict__ x) {
    int m = blockIdx.x;
    int tok = tokens[m];
    tok = min(max(tok, 0), 255);
    reinterpret_cast<float4*>(x + (size_t)m * DIM)[threadIdx.x] =
        reinterpret_cast<const float4*>(embed + (size_t)tok * DIM)[threadIdx.x];
}

__global__ void rmsnorm_bf16_kernel(const float* __restrict__ x,
                                    const float* __restrict__ w,
                                    bf16* __restrict__ oh, bf16* __restrict__ ol) {
    int row = blockIdx.x;
    const float4 v = reinterpret_cast<const float4*>(x + (size_t)row * DIM)[threadIdx.x];
    float ss = v.x * v.x + v.y * v.y + v.z * v.z + v.w * v.w;
    for (int s = 16; s; s >>= 1) ss += __shfl_xor_sync(0xffffffffu, ss, s);
    __shared__ float red[4];
    int lane = threadIdx.x & 31, wp = threadIdx.x >> 5;
    if (!lane) red[wp] = ss;
    __syncthreads();
    ss = red[0] + red[1] + red[2] + red[3];
    float rs = rsqrtf(ss * (1.0f / DIM) + EPSV);
    float4 wv = reinterpret_cast<const float4*>(w)[threadIdx.x];
    float4 r = make_float4(v.x * rs * wv.x, v.y * rs * wv.y,
                           v.z * rs * wv.z, v.w * rs * wv.w);
    uint2 hp, lp;
    split_pack(r, hp, lp);
    *reinterpret_cast<uint2*>(oh + (size_t)row * DIM + threadIdx.x * 4) = hp;
    *reinterpret_cast<uint2*>(ol + (size_t)row * DIM + threadIdx.x * 4) = lp;
}

__global__ void rmsnorm_f32_kernel(const float* __restrict__ x,
                                   const float* __restrict__ w,
                                   float* __restrict__ o) {
    int row = blockIdx.x;
    const float4 v = reinterpret_cast<const float4*>(x + (size_t)row * DIM)[threadIdx.x];
    float ss = v.x * v.x + v.y * v.y + v.z * v.z + v.w * v.w;
    for (int s = 16; s; s >>= 1) ss += __shfl_xor_sync(0xffffffffu, ss, s);
    __shared__ float red[4];
    int lane = threadIdx.x & 31, wp = threadIdx.x >> 5;
    if (!lane) red[wp] = ss;
    __syncthreads();
    ss = red[0] + red[1] + red[2] + red[3];
    float rs = rsqrtf(ss * (1.0f / DIM) + EPSV);
    float4 wv = reinterpret_cast<const float4*>(w)[threadIdx.x];
    float4 r = make_float4(v.x * rs * wv.x, v.y * rs * wv.y,
                           v.z * rs * wv.z, v.w * rs * wv.w);
    reinterpret_cast<float4*>(o + (size_t)row * DIM)[threadIdx.x] = r;
}

__global__ void rope_table_kernel(float* __restrict__ cosT, float* __restrict__ sinT) {
    int idx = blockIdx.x * blockDim.x + threadIdx.x;
    if (idx >= SEQ * HALFHD) return;
    int t = idx / HALFHD, i = idx % HALFHD;
    double inv = exp(-(double)i * (LOG_ROPE_BASE / (double)HALFHD));
    double ang = (double)t * inv;
    double s, c;
    sincos(ang, &s, &c);
    cosT[idx] = (float)c;
    sinT[idx] = (float)s;
}

constexpr int PACK_BLOCKS = (BSZ * NHEAD * SEQ * HALFHD) / 256;  // 2048
constexpr int VT_BLOCKS   = (SEQ / 32) * (HDIM / 32) * (BSZ * NHEAD); // 4096

__global__ void prep_attn_kernel(const float* __restrict__ qr,
                                 const float* __restrict__ kr,
                                 const float* __restrict__ vr,
                                 const float* __restrict__ cosT,
                                 const float* __restrict__ sinT,
                                 bf16* __restrict__ qph, bf16* __restrict__ qpl,
                                 bf16* __restrict__ kph, bf16* __restrict__ kpl,
                                 bf16* __restrict__ vth, bf16* __restrict__ vtl) {
    int tid = threadIdx.x;
    if (blockIdx.x < PACK_BLOCKS) {
        int gid = blockIdx.x * 256 + tid;
        int i = gid % HALFHD;
        int t = (gid / HALFHD) % SEQ;
        int h = (gid / (HALFHD * SEQ)) % NHEAD;
        int b = gid / (HALFHD * SEQ * NHEAD);
        size_t src = ((size_t)b * SEQ + t) * DIM + h * HDIM + 2 * i;
        size_t dst = (((size_t)(b * NHEAD + h)) * SEQ + t) * HDIM + 2 * i;
        float c = cosT[t * HALFHD + i];
        float s = sinT[t * HALFHD + i];
        float2 q2 = *reinterpret_cast<const float2*>(qr + src);
        float2 k2 = *reinterpret_cast<const float2*>(kr + src);
        const float qs = 0.125f;
        u32 hi, lo;
        split2((q2.x * c - q2.y * s) * qs, (q2.x * s + q2.y * c) * qs, hi, lo);
        *reinterpret_cast<u32*>(qph + dst) = hi;
        *reinterpret_cast<u32*>(qpl + dst) = lo;
        split2(k2.x * c - k2.y * s, k2.x * s + k2.y * c, hi, lo);
        *reinterpret_cast<u32*>(kph + dst) = hi;
        *reinterpret_cast<u32*>(kpl + dst) = lo;
    } else {
        __shared__ float smem_t[32][33];
        int bid = blockIdx.x - PACK_BLOCKS;
        int t0 = (bid & 63) * 32;
        int d0 = ((bid >> 6) & 1) * 32;
        int bh = bid >> 7;
        int b = bh >> 3, h = bh & 7;
        int tx = tid & 31, ty = tid >> 5;
#pragma unroll
        for (int r = 0; r < 32; r += 8)
            smem_t[ty + r][tx] =
                vr[((size_t)(b * SEQ) + t0 + ty + r) * DIM + h * HDIM + d0 + tx];
        __syncthreads();
#pragma unroll
        for (int r = 0; r < 32; r += 8) {
            float v = smem_t[tx][ty + r];
            bf16 hv = __float2bfloat16_rn(v);
            size_t o = ((size_t)bh * HDIM + d0 + ty + r) * SEQ + t0 + tx;
            vth[o] = hv;
            vtl[o] = __float2bfloat16_rn(v - __bfloat162float(hv));
        }
    }
}

__global__ void zero_kernel(float* __restrict__ p, size_t n) {
    size_t i = (size_t)blockIdx.x * blockDim.x + threadIdx.x;
    size_t stride = (size_t)gridDim.x * blockDim.x;
    for (; i < n; i += stride) p[i] = 0.0f;
}

__global__ void segscan_kernel(const int* __restrict__ tokens, int* __restrict__ seg) {
    int b = blockIdx.x;
    constexpr int PT = SEQ / 256;
    int flags[PT];
    int s = 0;
#pragma unroll
    for (int j = 0; j < PT; j++) {
        int tok = tokens[b * SEQ + threadIdx.x * PT + j];
        tok = min(max(tok, 0), 255);
        flags[j] = is_sep(tok) ? 1 : 0;
        s += flags[j];
    }
    __shared__ int wsum[8];
    int lane = threadIdx.x & 31, wp = threadIdx.x >> 5;
    int ps = s;
    for (int o = 1; o < 32; o <<= 1) {
        int v = __shfl_up_sync(0xffffffffu, ps, o);
        if (lane >= o) ps += v;
    }
    if (lane == 31) wsum[wp] = ps;
    __syncthreads();
    int woff = 0;
    for (int i = 0; i < wp; i++) woff += wsum[i];
    int run = ps - s + woff;
#pragma unroll
    for (int j = 0; j < PT; j++) {
        run += flags[j];
        seg[b * SEQ + threadIdx.x * PT + j] = run + b * (SEQ + 1);
    }
}

__global__ void segsum_kernel(const float* __restrict__ h, const int* __restrict__ seg,
                              float* __restrict__ ssum, float* __restrict__ scnt) {
    int m = blockIdx.x;
    int s = seg[m];
    float4 v = reinterpret_cast<const float4*>(h + (size_t)m * DIM)[threadIdx.x];
    float* base = ssum + (size_t)s * DIM + threadIdx.x * 4;
    atomicAdd(base + 0, v.x);
    atomicAdd(base + 1, v.y);
    atomicAdd(base + 2, v.z);
    atomicAdd(base + 3, v.w);
    if (threadIdx.x == 0) atomicAdd(scnt + s, 1.0f);
}

__global__ void pool_kernel(const float* __restrict__ h, const int* __restrict__ seg,
                            const float* __restrict__ ssum, const float* __restrict__ scnt,
                            float* __restrict__ out) {
    int m = blockIdx.x;
    int s = seg[m];
    float inv = 1.0f / fmaxf(scnt[s], 1.0f);
    float4 v = reinterpret_cast<const float4*>(h + (size_t)m * DIM)[threadIdx.x];
    float4 sm = reinterpret_cast<const float4*>(ssum + (size_t)s * DIM)[threadIdx.x];
    float4 r = make_float4(ALPHAV * v.x + (1.0f - ALPHAV) * sm.x * inv,
                           ALPHAV * v.y + (1.0f - ALPHAV) * sm.y * inv,
                           ALPHAV * v.z + (1.0f - ALPHAV) * sm.z * inv,
                           ALPHAV * v.w + (1.0f - ALPHAV) * sm.w * inv);
    reinterpret_cast<float4*>(out + (size_t)m * DIM)[threadIdx.x] = r;
}

// ---------------- fused flash attention (FT=128, pre-split, Q frags hoisted) ----------------
constexpr int FT = 128;
constexpr int LDQK = 144;
constexpr int LDV  = 272;
constexpr u32 SQH = 0;
constexpr u32 SQL = 18432;
constexpr u32 FKV0 = 36864;
constexpr u32 KPL = 18432;
constexpr u32 FVOFF = 36864;
constexpr u32 VPL = 17408;
constexpr u32 KVBUF = 71680;
constexpr int FLASH_SMEM = 36864 + 2 * 71680;  // 180224

__global__ void __launch_bounds__(256, 1)
flash_kernel(const bf16* __restrict__ qph, const bf16* __restrict__ qpl,
             const bf16* __restrict__ kph, const bf16* __restrict__ kpl,
             const bf16* __restrict__ vth, const bf16* __restrict__ vtl,
             bf16* __restrict__ och, bf16* __restrict__ ocl) {
    extern __shared__ __align__(16) char smem[];
    const u32 sb = smem_u32(smem);
    const int tid = threadIdx.x;
    const int lane = tid & 31, wid = tid >> 5;
    const int qt = blockIdx.x, bh = blockIdx.y;
    const int b = bh >> 3, h = bh & 7;

    const size_t qbase = ((size_t)bh * SEQ + qt * 128) * HDIM;
    const bf16* Kh = kph + (size_t)bh * SEQ * HDIM;
    const bf16* Kl = kpl + (size_t)bh * SEQ * HDIM;
    const bf16* Vh = vth + (size_t)bh * HDIM * SEQ;
    const bf16* Vl = vtl + (size_t)bh * HDIM * SEQ;

    auto kv_prefetch = [&](int tt, int buf) {
        u32 base = sb + FKV0 + (u32)buf * KVBUF;
#pragma unroll
        for (int i = 0; i < 8; i++) {
            int idx = tid + i * 256;
            int plane = idx >> 10;
            int rem = idx & 1023;
            int row = rem >> 3, hf = rem & 7;
            const bf16* src = (plane ? Kl : Kh) + (size_t)(tt * FT + row) * HDIM + hf * 8;
            cp16(base + plane * KPL + row * LDQK + hf * 16, src);
        }
#pragma unroll
        for (int i = 0; i < 8; i++) {
            int idx = tid + i * 256;
            int plane = idx >> 10;
            int rem = idx & 1023;
            int row = rem >> 4, hf = rem & 15;
            const bf16* src = (plane ? Vl : Vh) + (size_t)row * SEQ + tt * FT + hf * 8;
            cp16(base + FVOFF + plane * VPL + row * LDV + hf * 16, src);
        }
        cp_commit();
    };

#pragma unroll
    for (int i = 0; i < 8; i++) {
        int idx = tid + i * 256;
        int plane = idx >> 10;
        int rem = idx & 1023;
        int row = rem >> 3, hf = rem & 7;
        const bf16* src = (plane ? qpl : qph) + qbase + (size_t)row * HDIM + hf * 8;
        cp16(sb + (plane ? SQL : SQH) + row * LDQK + hf * 16, src);
    }
    kv_prefetch(0, 0);
    kv_prefetch(1, 1);

    float accO[8][4];
#pragma unroll
    for (int i = 0; i < 8; i++)
#pragma unroll
        for (int j = 0; j < 4; j++) accO[i][j] = 0.f;
    float m0 = -1e30f, m1 = -1e30f, l0 = 0.f, l1 = 0.f;

    const int arow = wid * 16 + (lane & 15);
    const int acol = ((lane >> 4) & 1) * 16;
    const int brow = lane & 7;
    const int bcol = ((lane >> 3) & 1) * 16;

    u32 qh[4][4], ql[4][4];

    constexpr int NTILE = SEQ / FT;
    for (int t = 0; t < NTILE; t++) {
        if (t == NTILE - 1) cp_wait0(); else cp_wait1();
        __syncthreads();

        if (t == 0) {
#pragma unroll
            for (int ks = 0; ks < 4; ks++) {
                u32 off = (u32)(arow * LDQK + ks * 32 + acol);
                ldsm4(sb + SQH + off, qh[ks][0], qh[ks][1], qh[ks][2], qh[ks][3]);
                ldsm4(sb + SQL + off, ql[ks][0], ql[ks][1], ql[ks][2], ql[ks][3]);
            }
        }

        const u32 kvb = sb + FKV0 + (u32)((t & 1) * KVBUF);
        const u32 sKH = kvb, sKL = kvb + KPL;
        const u32 sVH = kvb + FVOFF, sVL = kvb + FVOFF + VPL;

        float acc[16][4];
#pragma unroll
        for (int i = 0; i < 16; i++)
#pragma unroll
            for (int j = 0; j < 4; j++) acc[i][j] = 0.f;

#pragma unroll
        for (int nt = 0; nt < 16; nt++) {
#pragma unroll
            for (int ks = 0; ks < 4; ks++) {
                u32 off = (u32)((nt * 8 + brow) * LDQK + ks * 32 + bcol);
                u32 b0, b1, c0, c1;
                ldsm2(sKH + off, b0, b1);
                ldsm2(sKL + off, c0, c1);
                mma16816(acc[nt], qh[ks][0], qh[ks][1], qh[ks][2], qh[ks][3], b0, b1);
                mma16816(acc[nt], qh[ks][0], qh[ks][1], qh[ks][2], qh[ks][3], c0, c1);
                mma16816(acc[nt], ql[ks][0], ql[ks][1], ql[ks][2], ql[ks][3], b0, b1);
            }
        }

        float tm0 = -1e30f, tm1 = -1e30f;
#pragma unroll
        for (int nt = 0; nt < 16; nt++) {
            tm0 = fmaxf(tm0, fmaxf(acc[nt][0], acc[nt][1]));
            tm1 = fmaxf(tm1, fmaxf(acc[nt][2], acc[nt][3]));
        }
        tm0 = fmaxf(tm0, __shfl_xor_sync(0xffffffffu, tm0, 1));
        tm0 = fmaxf(tm0, __shfl_xor_sync(0xffffffffu, tm0, 2));
        tm1 = fmaxf(tm1, __shfl_xor_sync(0xffffffffu, tm1, 1));
        tm1 = fmaxf(tm1, __shfl_xor_sync(0xffffffffu, tm1, 2));
        float mn0 = fmaxf(m0, tm0), mn1 = fmaxf(m1, tm1);
        float a0 = __expf(m0 - mn0), a1 = __expf(m1 - mn1);
        m0 = mn0;
        m1 = mn1;
        float s0 = 0.f, s1 = 0.f;
#pragma unroll
        for (int nt = 0; nt < 16; nt++) {
            acc[nt][0] = __expf(acc[nt][0] - m0);
            acc[nt][1] = __expf(acc[nt][1] - m0);
            acc[nt][2] = __expf(acc[nt][2] - m1);
            acc[nt][3] = __expf(acc[nt][3] - m1);
            s0 += acc[nt][0] + acc[nt][1];
            s1 += acc[nt][2] + acc[nt][3];
        }
        s0 += __shfl_xor_sync(0xffffffffu, s0, 1);
        s0 += __shfl_xor_sync(0xffffffffu, s0, 2);
        s1 += __shfl_xor_sync(0xffffffffu, s1, 1);
        s1 += __shfl_xor_sync(0xffffffffu, s1, 2);
        l0 = l0 * a0 + s0;
        l1 = l1 * a1 + s1;
#pragma unroll
        for (int on = 0; on < 8; on++) {
            accO[on][0] *= a0;
            accO[on][1] *= a0;
            accO[on][2] *= a1;
            accO[on][3] *= a1;
        }

#pragma unroll
        for (int ks = 0; ks < 8; ks++) {
            u32 ah[4], al[4];
            split2(acc[2 * ks][0], acc[2 * ks][1], ah[0], al[0]);
            split2(acc[2 * ks][2], acc[2 * ks][3], ah[1], al[1]);
            split2(acc[2 * ks + 1][0], acc[2 * ks + 1][1], ah[2], al[2]);
            split2(acc[2 * ks + 1][2], acc[2 * ks + 1][3], ah[3], al[3]);
#pragma unroll
            for (int on = 0; on < 8; on++) {
                u32 off = (u32)((on * 8 + brow) * LDV + ks * 32 + bcol);
                u32 b0, b1, c0, c1;
                ldsm2(sVH + off, b0, b1);
                ldsm2(sVL + off, c0, c1);
                mma16816(accO[on], ah[0], ah[1], ah[2], ah[3], b0, b1);
                mma16816(accO[on], ah[0], ah[1], ah[2], ah[3], c0, c1);
                mma16816(accO[on], al[0], al[1], al[2], al[3], b0, b1);
            }
        }
        __syncthreads();
        if (t + 2 < NTILE) kv_prefetch(t + 2, t & 1);
    }

    float i0 = 1.0f / l0, i1 = 1.0f / l1;
    int t0 = qt * 128 + wid * 16 + (lane >> 2);
    size_t base0 = ((size_t)b * SEQ + t0) * DIM + h * HDIM;
    size_t base1 = ((size_t)b * SEQ + t0 + 8) * DIM + h * HDIM;
#pragma unroll
    for (int on = 0; on < 8; on++) {
        int d = on * 8 + (lane & 3) * 2;
        u32 hi, lo;
        split2(accO[on][0] * i0, accO[on][1] * i0, hi, lo);
        *reinterpret_cast<u32*>(och + base0 + d) = hi;
        *reinterpret_cast<u32*>(ocl + base0 + d) = lo;
        split2(accO[on][2] * i1, accO[on][3] * i1, hi, lo);
        *reinterpret_cast<u32*>(och + base1 + d) = hi;
        *reinterpret_cast<u32*>(ocl + base1 + d) = lo;
    }
}

// ---------------- warp-MMA GEMM, pre-split bf16 operands, BK=32 ----------------
struct PB3 { const bf16* p0; const bf16* p1; const bf16* p2; };

constexpr int GLDB = 80;                 // 32 bf16 = 64B data + 16 pad
constexpr int GPLANE = 128 * GLDB;       // 10240
constexpr int GSBUF = 4 * GPLANE;        // 40960
constexpr int GSMEM = 2 * GSBUF;         // 81920

__global__ void __launch_bounds__(128, 2)
gemm_mma_kernel(const bf16* __restrict__ Ah, PB3 BW,
                float* __restrict__ C, const float* __restrict__ R,
                int N, int K, size_t sCz, size_t aLoD, size_t bLoD) {
    extern __shared__ __align__(16) char smem[];
    const int tid = threadIdx.x;
    const int lane = tid & 31, wid = tid >> 5;
    const int wy = wid >> 1, wx = wid & 1;
    const u32 sbase = smem_u32(smem);

    const bf16* Bh = (blockIdx.z == 0) ? BW.p0 : (blockIdx.z == 1) ? BW.p1 : BW.p2;
    const bf16* Ab = Ah + (size_t)(blockIdx.y * 128) * K;
    const bf16* Bb = Bh + (size_t)(blockIdx.x * 128) * K;

    float acc[4][8][4];
#pragma unroll
    for (int i = 0; i < 4; i++)
#pragma unroll
        for (int j = 0; j < 8; j++)
#pragma unroll
            for (int q = 0; q < 4; q++) acc[i][j][q] = 0.f;

    const int nchunk = K >> 5;

    auto prefetch = [&](int c, int buf) {
        u32 sb = sbase + (u32)(buf * GSBUF);
        const bf16* Asrc = Ab + c * 32;
        const bf16* Bsrc = Bb + c * 32;
#pragma unroll
        for (int i = 0; i < 16; i++) {
            int idx = tid + i * 128;          // 0..2047
            int plane = idx >> 9;             // 0=Ah,1=Al,2=Bh,3=Bl
            int rem = idx & 511;
            int row = rem >> 2, hf = rem & 3;
            const bf16* src;
            if (plane == 0)      src = Asrc + (size_t)row * K + hf * 8;
            else if (plane == 1) src = Asrc + aLoD + (size_t)row * K + hf * 8;
            else if (plane == 2) src = Bsrc + (size_t)row * K + hf * 8;
            else                 src = Bsrc + bLoD + (size_t)row * K + hf * 8;
            cp16(sb + plane * GPLANE + row * GLDB + hf * 16, src);
        }
        cp_commit();
    };

    prefetch(0, 0);
    prefetch(1, 1);

    const int arow = wy * 64 + (lane & 15);
    const int acol = ((lane >> 4) & 1) * 16;
    const int brow0 = wx * 64 + (lane & 7);
    const int bcol = ((lane >> 3) & 1) * 16;

    for (int c = 0; c < nchunk; ++c) {
        if (c == nchunk - 1) cp_wait0(); else cp_wait1();
        __syncthreads();

        {
            u32 base = sbase + (u32)((c & 1) * GSBUF);
            u32 aH = base, aL = base + GPLANE;
            u32 bH = base + 2 * GPLANE, bL = base + 3 * GPLANE;

#pragma unroll
            for (int ks = 0; ks < 2; ++ks) {
                u32 ah[4][4], al[4][4];
#pragma unroll
                for (int mt = 0; mt < 4; ++mt) {
                    u32 off = (u32)((arow + mt * 16) * GLDB + ks * 32 + acol);
                    ldsm4(aH + off, ah[mt][0], ah[mt][1], ah[mt][2], ah[mt][3]);
                    ldsm4(aL + off, al[mt][0], al[mt][1], al[mt][2], al[mt][3]);
                }
#pragma unroll
                for (int g = 0; g < 2; ++g) {
                    u32 bh[4][2], bl[4][2];
#pragma unroll
                    for (int nt = 0; nt < 4; ++nt) {
                        u32 off = (u32)((brow0 + (g * 4 + nt) * 8) * GLDB + ks * 32 + bcol);
                        ldsm2(bH + off, bh[nt][0], bh[nt][1]);
                        ldsm2(bL + off, bl[nt][0], bl[nt][1]);
                    }
#pragma unroll
                    for (int mt = 0; mt < 4; ++mt)
#pragma unroll
                        for (int nt = 0; nt < 4; ++nt) {
                            float* a = acc[mt][g * 4 + nt];
                            mma16816(a, ah[mt][0], ah[mt][1], ah[mt][2], ah[mt][3],
                                     bh[nt][0], bh[nt][1]);
                            mma16816(a, ah[mt][0], ah[mt][1], ah[mt][2], ah[mt][3],
                                     bl[nt][0], bl[nt][1]);
                            mma16816(a, al[mt][0], al[mt][1], al[mt][2], al[mt][3],
                                     bh[nt][0], bh[nt][1]);
                        }
                }
            }
        }
        __syncthreads();
        if (c + 2 < nchunk) prefetch(c + 2, c & 1);
    }

    float* Cz = C + (size_t)blockIdx.z * sCz;
    const float* Rz = R;
#pragma unroll
    for (int mt = 0; mt < 4; ++mt) {
        int row0 = blockIdx.y * 128 + wy * 64 + mt * 16 + (lane >> 2);
#pragma unroll
        for (int nt = 0; nt < 8; ++nt) {
            int col = blockIdx.x * 128 + wx * 64 + nt * 8 + (lane & 3) * 2;
            size_t o0 = (size_t)row0 * N + col;
            size_t o1 = (size_t)(row0 + 8) * N + col;
            float2 v0 = make_float2(acc[mt][nt][0], acc[mt][nt][1]);
            float2 v1 = make_float2(acc[mt][nt][2], acc[mt][nt][3]);
            if (Rz) {
                float2 r0 = *reinterpret_cast<const float2*>(Rz + o0);
                float2 r1 = *reinterpret_cast<const float2*>(Rz + o1);
                v0.x += r0.x; v0.y += r0.y;
                v1.x += r1.x; v1.y += r1.y;
            }
            *reinterpret_cast<float2*>(Cz + o0) = v0;
            *reinterpret_cast<float2*>(Cz + o1) = v1;
        }
    }
}

// ---------------- fused W1/W3 GEMM with swiglu epilogue (BK=16, unchanged) ----------------
constexpr int WLDB  = 48;
constexpr int WAPL  = 128 * WLDB;
constexpr int WBPL  = 64 * WLDB;
constexpr int WSBUF = 2 * WAPL + 4 * WBPL;
constexpr int WSMEM = 2 * WSBUF;

__global__ void __launch_bounds__(128, 2)
gemm_w13_kernel(const bf16* __restrict__ Ah,
                const bf16* __restrict__ W1h, const bf16* __restrict__ W3h,
                bf16* __restrict__ gh, bf16* __restrict__ gl,
                int K, size_t aLoD, size_t bLoD) {
    extern __shared__ __align__(16) char smem[];
    const int tid = threadIdx.x;
    const int lane = tid & 31, wid = tid >> 5;
    const int wy = wid >> 1, wx = wid & 1;
    const u32 sbase = smem_u32(smem);

    const bf16* Ab = Ah + (size_t)(blockIdx.y * 128) * K;
    const bf16* B1 = W1h + (size_t)(blockIdx.x * 64) * K;
    const bf16* B3 = W3h + (size_t)(blockIdx.x * 64) * K;

    float acc1[4][4][4], acc3[4][4][4];
#pragma unroll
    for (int i = 0; i < 4; i++)
#pragma unroll
        for (int j = 0; j < 4; j++)
#pragma unroll
            for (int q = 0; q < 4; q++) { acc1[i][j][q] = 0.f; acc3[i][j][q] = 0.f; }

    const int nchunk = K >> 4;

    auto prefetch = [&](int c, int buf) {
        u32 sb = sbase + (u32)(buf * WSBUF);
        const bf16* Asrc = Ab + c * 16;
        const bf16* B1s = B1 + c * 16;
        const bf16* B3s = B3 + c * 16;
#pragma unroll
        for (int i = 0; i < 8; i++) {
            int idx = tid + i * 128;
            if (idx < 512) {
                int plane = idx >> 8;
                int rem = idx & 255;
                int row = rem >> 1, hf = rem & 1;
                const bf16* src = Asrc + (plane ? aLoD : 0) + (size_t)row * K + hf * 8;
                cp16(sb + plane * WAPL + row * WLDB + hf * 16, src);
            } else {
                int bidx = idx - 512;
                int plane = bidx >> 7;
                int rem = bidx & 127;
                int row = rem >> 1, hf = rem & 1;
                const bf16* src;
                if (plane == 0)      src = B1s + (size_t)row * K + hf * 8;
                else if (plane == 1) src = B1s + bLoD + (size_t)row * K + hf * 8;
                else if (plane == 2) src = B3s + (size_t)row * K + hf * 8;
                else                 src = B3s + bLoD + (size_t)row * K + hf * 8;
                cp16(sb + 2 * WAPL + plane * WBPL + row * WLDB + hf * 16, src);
            }
        }
        cp_commit();
    };

    prefetch(0, 0);
    prefetch(1, 1);

    const int arow = wy * 64 + (lane & 15);
    const int acol = ((lane >> 4) & 1) * 16;
    const int brow = wx * 32 + (lane & 7);
    const int bcol = ((lane >> 3) & 1) * 16;

    for (int c = 0; c < nchunk; ++c) {
        if (c == nchunk - 1) cp_wait0(); else cp_wait1();
        __syncthreads();

        {
            u32 base = sbase + (u32)((c & 1) * WSBUF);
            u32 aH = base, aL = base + WAPL;
            u32 b1H = base + 2 * WAPL;
            u32 b1L = b1H + WBPL;
            u32 b3H = b1L + WBPL;
            u32 b3L = b3H + WBPL;

            u32 ah[4][4], al[4][4];
#pragma unroll
            for (int mt = 0; mt < 4; ++mt) {
                u32 off = (u32)((arow + mt * 16) * WLDB + acol);
                ldsm4(aH + off, ah[mt][0], ah[mt][1], ah[mt][2], ah[mt][3]);
                ldsm4(aL + off, al[mt][0], al[mt][1], al[mt][2], al[mt][3]);
            }
            {
                u32 bh[4][2], bl[4][2];
#pragma unroll
                for (int nt = 0; nt < 4; ++nt) {
                    u32 off = (u32)((brow + nt * 8) * WLDB + bcol);
                    ldsm2(b1H + off, bh[nt][0], bh[nt][1]);
                    ldsm2(b1L + off, bl[nt][0], bl[nt][1]);
                }
#pragma unroll
                for (int mt = 0; mt < 4; ++mt)
#pragma unroll
                    for (int nt = 0; nt < 4; ++nt) {
                        float* a = acc1[mt][nt];
                        mma16816(a, ah[mt][0], ah[mt][1], ah[mt][2], ah[mt][3],
                                 bh[nt][0], bh[nt][1]);
                        mma16816(a, ah[mt][0], ah[mt][1], ah[mt][2], ah[mt][3],
                                 bl[nt][0], bl[nt][1]);
                        mma16816(a, al[mt][0], al[mt][1], al[mt][2], al[mt][3],
                                 bh[nt][0], bh[nt][1]);
                    }
            }
            {
                u32 bh[4][2], bl[4][2];
#pragma unroll
                for (int nt = 0; nt < 4; ++nt) {
                    u32 off = (u32)((brow + nt * 8) * WLDB + bcol);
                    ldsm2(b3H + off, bh[nt][0], bh[nt][1]);
                    ldsm2(b3L + off, bl[nt][0], bl[nt][1]);
                }
#pragma unroll
                for (int mt = 0; mt < 4; ++mt)
#pragma unroll
                    for (int nt = 0; nt < 4; ++nt) {
                        float* a = acc3[mt][nt];
                        mma16816(a, ah[mt][0], ah[mt][1], ah[mt][2], ah[mt][3],
                                 bh[nt][0], bh[nt][1]);
                        mma16816(a, ah[mt][0], ah[mt][1], ah[mt][2], ah[mt][3],
                                 bl[nt][0], bl[nt][1]);
                        mma16816(a, al[mt][0], al[mt][1], al[mt][2], al[mt][3],
                                 bh[nt][0], bh[nt][1]);
                    }
            }
        }
        __syncthreads();
        if (c + 2 < nchunk) prefetch(c + 2, c & 1);
    }

#pragma unroll
    for (int mt = 0; mt < 4; ++mt) {
        int row0 = blockIdx.y * 128 + wy * 64 + mt * 16 + (lane >> 2);
#pragma unroll
        for (int nt = 0; nt < 4; ++nt) {
            int col = blockIdx.x * 64 + wx * 32 + nt * 8 + (lane & 3) * 2;
            size_t o0 = (size_t)row0 * FFDIM + col;
            size_t o1 = (size_t)(row0 + 8) * FFDIM + col;
            float a0 = acc1[mt][nt][0], a1 = acc1[mt][nt][1];
            float a2 = acc1[mt][nt][2], a3 = acc1[mt][nt][3];
            float g0 = a0 / (1.0f + __expf(-a0)) * acc3[mt][nt][0];
            float g1 = a1 / (1.0f + __expf(-a1)) * acc3[mt][nt][1];
            float g2 = a2 / (1.0f + __expf(-a2)) * acc3[mt][nt][2];
            float g3 = a3 / (1.0f + __expf(-a3)) * acc3[mt][nt][3];
            u32 hi, lo;
            split2(g0, g1, hi, lo);
            *reinterpret_cast<u32*>(gh + o0) = hi;
            *reinterpret_cast<u32*>(gl + o0) = lo;
            split2(g2, g3, hi, lo);
            *reinterpret_cast<u32*>(gh + o1) = hi;
            *reinterpret_cast<u32*>(gl + o1) = lo;
        }
    }
}

// ---------------- host ----------------
extern "C" void kernel_launch(void* const* d_in, const int* in_sizes, int n_in,
                              void* d_out, int out_size) {
    const int*   tokens       = (const int*)d_in[0];
    const float* embed        = (const float*)d_in[1];
    const float* attn_norm_w  = (const float*)d_in[2];
    const float* wq           = (const float*)d_in[3];
    const float* wk           = (const float*)d_in[4];
    const float* wv           = (const float*)d_in[5];
    const float* wo           = (const float*)d_in[6];
    const float* ffn_norm_w   = (const float*)d_in[7];
    const float* w1           = (const float*)d_in[8];
    const float* w2           = (const float*)d_in[9];
    const float* w3           = (const float*)d_in[10];
    const float* final_norm_w = (const float*)d_in[11];
    float* out = (float*)d_out;

    cudaFuncSetAttribute(gemm_mma_kernel,
                         cudaFuncAttributeMaxDynamicSharedMemorySize, GSMEM);
    cudaFuncSetAttribute(gemm_w13_kernel,
                         cudaFuncAttributeMaxDynamicSharedMemorySize, WSMEM);
    cudaFuncSetAttribute(flash_kernel,
                         cudaFuncAttributeMaxDynamicSharedMemorySize, FLASH_SMEM);

    float* buf = nullptr;
    cudaGetSymbolAddress((void**)&buf, g_buf);
    int* seg = nullptr;
    cudaGetSymbolAddress((void**)&seg, g_seg);
    bf16* ab = nullptr;
    cudaGetSymbolAddress((void**)&ab, g_abuf);
    bf16* ws = nullptr;
    cudaGetSymbolAddress((void**)&ws, g_wsplit);

    float* x    = buf + OFF_X;
    float* y    = buf + OFF_Y;
    float* qr   = buf + OFF_Q;
    float* kr   = buf + OFF_K;
    float* vr   = buf + OFF_V;
    float* hf   = buf + OFF_HF;
    float* ssum = buf + OFF_SSUM;
    float* scnt = buf + OFF_SCNT;
    float* cosT = buf + OFF_COS;
    float* sinT = buf + OFF_SIN;

    bf16* xnh = ab + BXN;
    bf16* och = ab + BOC;
    bf16* qph = ab + BQP;
    bf16* kph = ab + BKP;
    bf16* vth = ab + BVT;
    bf16* ggh = ab + BGG;

    WSrc wsrc{{wq, wk, wv, wo, w1, w3, w2}};
    wsplit_all_kernel<<<(int)((TOT4 + 255) / 256), 256>>>(wsrc, ws);

    embed_kernel<<<BT, 128>>>(tokens, embed, x);
    rope_table_kernel<<<(SEQ * HALFHD + 255) / 256, 256>>>(cosT, sinT);

    for (int l = 0; l < NLAYER; l++) {
        const bf16* wqh = ws + WQO + (size_t)l * DIM * DIM;
        const bf16* wkh = ws + WKO + (size_t)l * DIM * DIM;
        const bf16* wvh = ws + WVO + (size_t)l * DIM * DIM;
        const bf16* woh = ws + WOO + (size_t)l * DIM * DIM;
        const bf16* w1h = ws + W1O + (size_t)l * FFDIM * DIM;
        const bf16* w3h = ws + W3O + (size_t)l * FFDIM * DIM;
        const bf16* w2h = ws + W2O + (size_t)l * DIM * FFDIM;

        rmsnorm_bf16_kernel<<<BT, 128>>>(x, attn_norm_w + (size_t)l * DIM,
                                         xnh, xnh + NX);

        dim3 gqkv(DIM / 128, BT / 128, 3);
        gemm_mma_kernel<<<gqkv, 128, GSMEM>>>(xnh, PB3{wqh, wkh, wvh},
                                              qr, nullptr, DIM, DIM, NX, NX, NPROJ);

        prep_attn_kernel<<<PACK_BLOCKS + VT_BLOCKS, 256>>>(
            qr, kr, vr, cosT, sinT,
            qph, qph + NX, kph, kph + NX, vth, vth + NX);

        flash_kernel<<<dim3(SEQ / 128, BSZ * NHEAD), 256, FLASH_SMEM>>>(
            qph, qph + NX, kph, kph + NX, vth, vth + NX, och, och + NX);

        dim3 gproj(DIM / 128, BT / 128, 1);
        gemm_mma_kernel<<<gproj, 128, GSMEM>>>(och, PB3{woh, woh, woh},
                                               y, x, DIM, DIM, 0, NX, NPROJ);

        rmsnorm_bf16_kernel<<<BT, 128>>>(y, ffn_norm_w + (size_t)l * DIM,
                                         xnh, xnh + NX);

        dim3 g13(FFDIM / 64, BT / 128, 1);
        gemm_w13_kernel<<<g13, 128, WSMEM>>>(xnh, w1h, w3h, ggh, ggh + NHID,
                                             DIM, NX, NFF);

        gemm_mma_kernel<<<gproj, 128, GSMEM>>>(ggh, PB3{w2h, w2h, w2h},
                                               x, y, DIM, FFDIM, 0, NHID, NFF);
    }

    rmsnorm_f32_kernel<<<BT, 128>>>(x, final_norm_w, hf);

    segscan_kernel<<<BSZ, 256>>>(tokens, seg);
    zero_kernel<<<4096, 256>>>(ssum, NSEGS + NSEGC);
    segsum_kernel<<<BT, 128>>>(hf, seg, ssum, scnt);
    pool_kernel<<<BT, 128>>>(hf, seg, ssum, scnt, out);
}

// round 14
// speedup vs baseline: 1.0672x; 1.0672x over previous
#include <cuda_runtime.h>
#include <cuda_bf16.h>
#include <math.h>

// Problem constants
#define BSZ 4
#define SEQ 2048
#define DIM 512
#define NHEAD 8
#define NLAYER 4
#define FFDIM 2048
#define HDIM 64
#define HALFHD 32
#define EPSV 1e-6f
#define ALPHAV 0.5f
#define LOG_ROPE_BASE 9.210340371976184   // ln(10000)

#define BT (BSZ * SEQ)                    // 8192

typedef unsigned int u32;
typedef unsigned long long u64;
typedef __nv_bfloat16 bf16;

// ---------------- scratch buffers ----------------
constexpr size_t NX    = (size_t)BT * DIM;
constexpr size_t NHID  = (size_t)BT * FFDIM;
constexpr size_t NSEGS = (size_t)BSZ * (SEQ + 1) * DIM;
constexpr size_t NSEGC = (size_t)BSZ * (SEQ + 1);
constexpr size_t NROPE = (size_t)SEQ * HALFHD;

constexpr size_t OFF_X    = 0;
constexpr size_t OFF_Y    = OFF_X  + NX;
constexpr size_t OFF_Q    = OFF_Y  + NX;   // qr,kr,vr contiguous (fused QKV)
constexpr size_t OFF_K    = OFF_Q  + NX;
constexpr size_t OFF_V    = OFF_K  + NX;
constexpr size_t OFF_HF   = OFF_V  + NX;
constexpr size_t OFF_SSUM = OFF_HF + NX;
constexpr size_t OFF_SCNT = OFF_SSUM + NSEGS;
constexpr size_t OFF_COS  = OFF_SCNT + NSEGC;
constexpr size_t OFF_SIN  = OFF_COS + NROPE;
constexpr size_t TOTALF   = OFF_SIN + NROPE;

__device__ float g_buf[TOTALF];
__device__ int   g_seg[BT];

// bf16 activation planes (hi plane, then lo plane at +delta)
constexpr size_t BXN = 0;
constexpr size_t BOC = 2 * NX;
constexpr size_t BQP = 4 * NX;
constexpr size_t BKP = 6 * NX;
constexpr size_t BVT = 8 * NX;
constexpr size_t BGG = 10 * NX;
constexpr size_t TOTALB = 10 * NX + 2 * NHID;
__device__ bf16 g_abuf[TOTALB];

// bf16 split weights
constexpr size_t NPROJ = (size_t)NLAYER * DIM * DIM;
constexpr size_t NFF   = (size_t)NLAYER * FFDIM * DIM;
constexpr size_t WQO = 0;
constexpr size_t WKO = 2 * NPROJ;
constexpr size_t WVO = 4 * NPROJ;
constexpr size_t WOO = 6 * NPROJ;
constexpr size_t W1O = 8 * NPROJ;
constexpr size_t W3O = W1O + 2 * NFF;
constexpr size_t W2O = W3O + 2 * NFF;
constexpr size_t TOTALW = W2O + 2 * NFF;
__device__ bf16 g_wsplit[TOTALW];

// ---------------- PTX helpers ----------------
__device__ __forceinline__ u32 smem_u32(const void* p) {
    u32 a;
    asm("{ .reg .u64 t; cvta.to.shared.u64 t, %1; cvt.u32.u64 %0, t; }" : "=r"(a) : "l"(p));
    return a;
}
__device__ __forceinline__ void ldsm4(u32 addr, u32& r0, u32& r1, u32& r2, u32& r3) {
    asm volatile("ldmatrix.sync.aligned.m8n8.x4.shared.b16 {%0,%1,%2,%3}, [%4];"
                 : "=r"(r0), "=r"(r1), "=r"(r2), "=r"(r3) : "r"(addr));
}
__device__ __forceinline__ void ldsm2(u32 addr, u32& r0, u32& r1) {
    asm volatile("ldmatrix.sync.aligned.m8n8.x2.shared.b16 {%0,%1}, [%2];"
                 : "=r"(r0), "=r"(r1) : "r"(addr));
}
__device__ __forceinline__ void mma16816(float* d, u32 a0, u32 a1, u32 a2, u32 a3,
                                         u32 b0, u32 b1) {
    asm volatile(
        "mma.sync.aligned.m16n8k16.row.col.f32.bf16.bf16.f32 "
        "{%0,%1,%2,%3}, {%4,%5,%6,%7}, {%8,%9}, {%0,%1,%2,%3};"
        : "+f"(d[0]), "+f"(d[1]), "+f"(d[2]), "+f"(d[3])
        : "r"(a0), "r"(a1), "r"(a2), "r"(a3), "r"(b0), "r"(b1));
}
__device__ __forceinline__ void cp16(u32 dst, const void* src) {
    asm volatile("cp.async.cg.shared.global [%0], [%1], 16;" :: "r"(dst), "l"(src));
}
__device__ __forceinline__ void cp_commit() { asm volatile("cp.async.commit_group;"); }
__device__ __forceinline__ void cp_wait0()  { asm volatile("cp.async.wait_group 0;" ::: "memory"); }
__device__ __forceinline__ void cp_wait1()  { asm volatile("cp.async.wait_group 1;" ::: "memory"); }

__device__ __forceinline__ void split_pack(float4 v, uint2& hp, uint2& lp) {
    __nv_bfloat162 h01, h23, l01, l23;
    h01.x = __float2bfloat16_rn(v.x);
    h01.y = __float2bfloat16_rn(v.y);
    h23.x = __float2bfloat16_rn(v.z);
    h23.y = __float2bfloat16_rn(v.w);
    l01.x = __float2bfloat16_rn(v.x - __bfloat162float(h01.x));
    l01.y = __float2bfloat16_rn(v.y - __bfloat162float(h01.y));
    l23.x = __float2bfloat16_rn(v.z - __bfloat162float(h23.x));
    l23.y = __float2bfloat16_rn(v.w - __bfloat162float(h23.y));
    hp.x = *reinterpret_cast<u32*>(&h01);
    hp.y = *reinterpret_cast<u32*>(&h23);
    lp.x = *reinterpret_cast<u32*>(&l01);
    lp.y = *reinterpret_cast<u32*>(&l23);
}
__device__ __forceinline__ void split2(float x, float y, u32& hi, u32& lo) {
    __nv_bfloat162 h, l;
    h.x = __float2bfloat16_rn(x);
    h.y = __float2bfloat16_rn(y);
    l.x = __float2bfloat16_rn(x - __bfloat162float(h.x));
    l.y = __float2bfloat16_rn(y - __bfloat162float(h.y));
    hi = *reinterpret_cast<u32*>(&h);
    lo = *reinterpret_cast<u32*>(&l);
}

__device__ __forceinline__ bool is_sep(int c) {
    switch (c) {
        case 9: case 10: case 13: case 32: case 33: case 34: case 35: case 36:
        case 37: case 38: case 39: case 40: case 41: case 42: case 43: case 44:
        case 45: case 46: case 47: case 58: case 59: case 60: case 61: case 62:
        case 63: case 64: case 91: case 92: case 93: case 94: case 123:
        case 124: case 125: case 126:
            return true;
        default:
            return false;
    }
}

// ---------------- small kernels ----------------
struct WSrc { const float* s[7]; };
constexpr size_t P4 = NPROJ / 4;
constexpr size_t F4 = NFF / 4;
constexpr size_t TOT4 = 4 * P4 + 3 * F4;

__global__ void wsplit_all_kernel(WSrc src, bf16* __restrict__ ws) {
    size_t i4 = (size_t)blockIdx.x * blockDim.x + threadIdx.x;
    if (i4 >= TOT4) return;
    int r;
    size_t local;
    bf16 *hi, *lo;
    const float* s;
    if (i4 < 4 * P4) {
        r = (int)(i4 / P4);
        local = i4 - (size_t)r * P4;
        s = src.s[r];
        hi = ws + (size_t)r * 2 * NPROJ;
        lo = hi + NPROJ;
    } else {
        size_t j = i4 - 4 * P4;
        r = (int)(j / F4);
        local = j - (size_t)r * F4;
        s = src.s[4 + r];
        hi = ws + W1O + (size_t)r * 2 * NFF;
        lo = hi + NFF;
    }
    float4 v = reinterpret_cast<const float4*>(s)[local];
    uint2 hp, lp;
    split_pack(v, hp, lp);
    *reinterpret_cast<uint2*>(hi + local * 4) = hp;
    *reinterpret_cast<uint2*>(lo + local * 4) = lp;
}

__global__ void embed_kernel(const int* __restrict__ tokens,
                             const float* __restrict__ embed,
                             float* __restrict__ x) {
    int m = blockIdx.x;
    int tok = tokens[m];
    tok = min(max(tok, 0), 255);
    reinterpret_cast<float4*>(x + (size_t)m * DIM)[threadIdx.x] =
        reinterpret_cast<const float4*>(embed + (size_t)tok * DIM)[threadIdx.x];
}

// rmsnorm -> bf16 hi/lo planes; each block loops over RPB rows
constexpr int RPB = 4;

__global__ void rmsnorm_bf16_kernel(const float* __restrict__ x,
                                    const float* __restrict__ w,
                                    bf16* __restrict__ oh, bf16* __restrict__ ol) {
    __shared__ float red[4];
    float4 wv = reinterpret_cast<const float4*>(w)[threadIdx.x];
    int lane = threadIdx.x & 31, wp = threadIdx.x >> 5;
#pragma unroll
    for (int rr = 0; rr < RPB; rr++) {
        int row = blockIdx.x * RPB + rr;
        const float4 v = reinterpret_cast<const float4*>(x + (size_t)row * DIM)[threadIdx.x];
        float ss = v.x * v.x + v.y * v.y + v.z * v.z + v.w * v.w;
        for (int s = 16; s; s >>= 1) ss += __shfl_xor_sync(0xffffffffu, ss, s);
        if (!lane) red[wp] = ss;
        __syncthreads();
        ss = red[0] + red[1] + red[2] + red[3];
        __syncthreads();
        float rs = rsqrtf(ss * (1.0f / DIM) + EPSV);
        float4 r = make_float4(v.x * rs * wv.x, v.y * rs * wv.y,
                               v.z * rs * wv.z, v.w * rs * wv.w);
        uint2 hp, lp;
        split_pack(r, hp, lp);
        *reinterpret_cast<uint2*>(oh + (size_t)row * DIM + threadIdx.x * 4) = hp;
        *reinterpret_cast<uint2*>(ol + (size_t)row * DIM + threadIdx.x * 4) = lp;
    }
}

__global__ void rmsnorm_f32_kernel(const float* __restrict__ x,
                                   const float* __restrict__ w,
                                   float* __restrict__ o) {
    __shared__ float red[4];
    float4 wv = reinterpret_cast<const float4*>(w)[threadIdx.x];
    int lane = threadIdx.x & 31, wp = threadIdx.x >> 5;
#pragma unroll
    for (int rr = 0; rr < RPB; rr++) {
        int row = blockIdx.x * RPB + rr;
        const float4 v = reinterpret_cast<const float4*>(x + (size_t)row * DIM)[threadIdx.x];
        float ss = v.x * v.x + v.y * v.y + v.z * v.z + v.w * v.w;
        for (int s = 16; s; s >>= 1) ss += __shfl_xor_sync(0xffffffffu, ss, s);
        if (!lane) red[wp] = ss;
        __syncthreads();
        ss = red[0] + red[1] + red[2] + red[3];
        __syncthreads();
        float rs = rsqrtf(ss * (1.0f / DIM) + EPSV);
        float4 r = make_float4(v.x * rs * wv.x, v.y * rs * wv.y,
                               v.z * rs * wv.z, v.w * rs * wv.w);
        reinterpret_cast<float4*>(o + (size_t)row * DIM)[threadIdx.x] = r;
    }
}

__global__ void rope_table_kernel(float* __restrict__ cosT, float* __restrict__ sinT) {
    int idx = blockIdx.x * blockDim.x + threadIdx.x;
    if (idx >= SEQ * HALFHD) return;
    int t = idx / HALFHD, i = idx % HALFHD;
    double inv = exp(-(double)i * (LOG_ROPE_BASE / (double)HALFHD));
    double ang = (double)t * inv;
    double s, c;
    sincos(ang, &s, &c);
    cosT[idx] = (float)c;
    sinT[idx] = (float)s;
}

constexpr int PACK_BLOCKS = (BSZ * NHEAD * SEQ * HALFHD) / 256;  // 2048
constexpr int VT_BLOCKS   = (SEQ / 32) * (HDIM / 32) * (BSZ * NHEAD); // 4096

__global__ void prep_attn_kernel(const float* __restrict__ qr,
                                 const float* __restrict__ kr,
                                 const float* __restrict__ vr,
                                 const float* __restrict__ cosT,
                                 const float* __restrict__ sinT,
                                 bf16* __restrict__ qph, bf16* __restrict__ qpl,
                                 bf16* __restrict__ kph, bf16* __restrict__ kpl,
                                 bf16* __restrict__ vth, bf16* __restrict__ vtl) {
    int tid = threadIdx.x;
    if (blockIdx.x < PACK_BLOCKS) {
        int gid = blockIdx.x * 256 + tid;
        int i = gid % HALFHD;
        int t = (gid / HALFHD) % SEQ;
        int h = (gid / (HALFHD * SEQ)) % NHEAD;
        int b = gid / (HALFHD * SEQ * NHEAD);
        size_t src = ((size_t)b * SEQ + t) * DIM + h * HDIM + 2 * i;
        size_t dst = (((size_t)(b * NHEAD + h)) * SEQ + t) * HDIM + 2 * i;
        float c = cosT[t * HALFHD + i];
        float s = sinT[t * HALFHD + i];
        float2 q2 = *reinterpret_cast<const float2*>(qr + src);
        float2 k2 = *reinterpret_cast<const float2*>(kr + src);
        const float qs = 0.125f;
        u32 hi, lo;
        split2((q2.x * c - q2.y * s) * qs, (q2.x * s + q2.y * c) * qs, hi, lo);
        *reinterpret_cast<u32*>(qph + dst) = hi;
        *reinterpret_cast<u32*>(qpl + dst) = lo;
        split2(k2.x * c - k2.y * s, k2.x * s + k2.y * c, hi, lo);
        *reinterpret_cast<u32*>(kph + dst) = hi;
        *reinterpret_cast<u32*>(kpl + dst) = lo;
    } else {
        __shared__ float smem_t[32][33];
        int bid = blockIdx.x - PACK_BLOCKS;
        int t0 = (bid & 63) * 32;
        int d0 = ((bid >> 6) & 1) * 32;
        int bh = bid >> 7;
        int b = bh >> 3, h = bh & 7;
        int tx = tid & 31, ty = tid >> 5;
#pragma unroll
        for (int r = 0; r < 32; r += 8)
            smem_t[ty + r][tx] =
                vr[((size_t)(b * SEQ) + t0 + ty + r) * DIM + h * HDIM + d0 + tx];
        __syncthreads();
#pragma unroll
        for (int r = 0; r < 32; r += 8) {
            float v = smem_t[tx][ty + r];
            bf16 hv = __float2bfloat16_rn(v);
            size_t o = ((size_t)bh * HDIM + d0 + ty + r) * SEQ + t0 + tx;
            vth[o] = hv;
            vtl[o] = __float2bfloat16_rn(v - __bfloat162float(hv));
        }
    }
}

__global__ void zero_kernel(float* __restrict__ p, size_t n) {
    size_t i = (size_t)blockIdx.x * blockDim.x + threadIdx.x;
    size_t stride = (size_t)gridDim.x * blockDim.x;
    for (; i < n; i += stride) p[i] = 0.0f;
}

__global__ void segscan_kernel(const int* __restrict__ tokens, int* __restrict__ seg) {
    int b = blockIdx.x;
    constexpr int PT = SEQ / 256;
    int flags[PT];
    int s = 0;
#pragma unroll
    for (int j = 0; j < PT; j++) {
        int tok = tokens[b * SEQ + threadIdx.x * PT + j];
        tok = min(max(tok, 0), 255);
        flags[j] = is_sep(tok) ? 1 : 0;
        s += flags[j];
    }
    __shared__ int wsum[8];
    int lane = threadIdx.x & 31, wp = threadIdx.x >> 5;
    int ps = s;
    for (int o = 1; o < 32; o <<= 1) {
        int v = __shfl_up_sync(0xffffffffu, ps, o);
        if (lane >= o) ps += v;
    }
    if (lane == 31) wsum[wp] = ps;
    __syncthreads();
    int woff = 0;
    for (int i = 0; i < wp; i++) woff += wsum[i];
    int run = ps - s + woff;
#pragma unroll
    for (int j = 0; j < PT; j++) {
        run += flags[j];
        seg[b * SEQ + threadIdx.x * PT + j] = run + b * (SEQ + 1);
    }
}

__global__ void segsum_kernel(const float* __restrict__ h, const int* __restrict__ seg,
                              float* __restrict__ ssum, float* __restrict__ scnt) {
    int m = blockIdx.x;
    int s = seg[m];
    float4 v = reinterpret_cast<const float4*>(h + (size_t)m * DIM)[threadIdx.x];
    float* base = ssum + (size_t)s * DIM + threadIdx.x * 4;
    atomicAdd(base + 0, v.x);
    atomicAdd(base + 1, v.y);
    atomicAdd(base + 2, v.z);
    atomicAdd(base + 3, v.w);
    if (threadIdx.x == 0) atomicAdd(scnt + s, 1.0f);
}

__global__ void pool_kernel(const float* __restrict__ h, const int* __restrict__ seg,
                            const float* __restrict__ ssum, const float* __restrict__ scnt,
                            float* __restrict__ out) {
    int m = blockIdx.x;
    int s = seg[m];
    float inv = 1.0f / fmaxf(scnt[s], 1.0f);
    float4 v = reinterpret_cast<const float4*>(h + (size_t)m * DIM)[threadIdx.x];
    float4 sm = reinterpret_cast<const float4*>(ssum + (size_t)s * DIM)[threadIdx.x];
    float4 r = make_float4(ALPHAV * v.x + (1.0f - ALPHAV) * sm.x * inv,
                           ALPHAV * v.y + (1.0f - ALPHAV) * sm.y * inv,
                           ALPHAV * v.z + (1.0f - ALPHAV) * sm.z * inv,
                           ALPHAV * v.w + (1.0f - ALPHAV) * sm.w * inv);
    reinterpret_cast<float4*>(out + (size_t)m * DIM)[threadIdx.x] = r;
}

// ---------------- fused flash attention (FT=128, pre-split, Q frags hoisted) ----------------
constexpr int FT = 128;
constexpr int LDQK = 144;
constexpr int LDV  = 272;
constexpr u32 SQH = 0;
constexpr u32 SQL = 18432;
constexpr u32 FKV0 = 36864;
constexpr u32 KPL = 18432;
constexpr u32 FVOFF = 36864;
constexpr u32 VPL = 17408;
constexpr u32 KVBUF = 71680;
constexpr int FLASH_SMEM = 36864 + 2 * 71680;  // 180224

__global__ void __launch_bounds__(256, 1)
flash_kernel(const bf16* __restrict__ qph, const bf16* __restrict__ qpl,
             const bf16* __restrict__ kph, const bf16* __restrict__ kpl,
             const bf16* __restrict__ vth, const bf16* __restrict__ vtl,
             bf16* __restrict__ och, bf16* __restrict__ ocl) {
    extern __shared__ __align__(16) char smem[];
    const u32 sb = smem_u32(smem);
    const int tid = threadIdx.x;
    const int lane = tid & 31, wid = tid >> 5;
    const int qt = blockIdx.x, bh = blockIdx.y;
    const int b = bh >> 3, h = bh & 7;

    const size_t qbase = ((size_t)bh * SEQ + qt * 128) * HDIM;
    const bf16* Kh = kph + (size_t)bh * SEQ * HDIM;
    const bf16* Kl = kpl + (size_t)bh * SEQ * HDIM;
    const bf16* Vh = vth + (size_t)bh * HDIM * SEQ;
    const bf16* Vl = vtl + (size_t)bh * HDIM * SEQ;

    auto kv_prefetch = [&](int tt, int buf) {
        u32 base = sb + FKV0 + (u32)buf * KVBUF;
#pragma unroll
        for (int i = 0; i < 8; i++) {
            int idx = tid + i * 256;
            int plane = idx >> 10;
            int rem = idx & 1023;
            int row = rem >> 3, hf = rem & 7;
            const bf16* src = (plane ? Kl : Kh) + (size_t)(tt * FT + row) * HDIM + hf * 8;
            cp16(base + plane * KPL + row * LDQK + hf * 16, src);
        }
#pragma unroll
        for (int i = 0; i < 8; i++) {
            int idx = tid + i * 256;
            int plane = idx >> 10;
            int rem = idx & 1023;
            int row = rem >> 4, hf = rem & 15;
            const bf16* src = (plane ? Vl : Vh) + (size_t)row * SEQ + tt * FT + hf * 8;
            cp16(base + FVOFF + plane * VPL + row * LDV + hf * 16, src);
        }
        cp_commit();
    };

#pragma unroll
    for (int i = 0; i < 8; i++) {
        int idx = tid + i * 256;
        int plane = idx >> 10;
        int rem = idx & 1023;
        int row = rem >> 3, hf = rem & 7;
        const bf16* src = (plane ? qpl : qph) + qbase + (size_t)row * HDIM + hf * 8;
        cp16(sb + (plane ? SQL : SQH) + row * LDQK + hf * 16, src);
    }
    kv_prefetch(0, 0);
    kv_prefetch(1, 1);

    float accO[8][4];
#pragma unroll
    for (int i = 0; i < 8; i++)
#pragma unroll
        for (int j = 0; j < 4; j++) accO[i][j] = 0.f;
    float m0 = -1e30f, m1 = -1e30f, l0 = 0.f, l1 = 0.f;

    const int arow = wid * 16 + (lane & 15);
    const int acol = ((lane >> 4) & 1) * 16;
    const int brow = lane & 7;
    const int bcol = ((lane >> 3) & 1) * 16;

    u32 qh[4][4], ql[4][4];

    constexpr int NTILE = SEQ / FT;
    for (int t = 0; t < NTILE; t++) {
        if (t == NTILE - 1) cp_wait0(); else cp_wait1();
        __syncthreads();

        if (t == 0) {
#pragma unroll
            for (int ks = 0; ks < 4; ks++) {
                u32 off = (u32)(arow * LDQK + ks * 32 + acol);
                ldsm4(sb + SQH + off, qh[ks][0], qh[ks][1], qh[ks][2], qh[ks][3]);
                ldsm4(sb + SQL + off, ql[ks][0], ql[ks][1], ql[ks][2], ql[ks][3]);
            }
        }

        const u32 kvb = sb + FKV0 + (u32)((t & 1) * KVBUF);
        const u32 sKH = kvb, sKL = kvb + KPL;
        const u32 sVH = kvb + FVOFF, sVL = kvb + FVOFF + VPL;

        float acc[16][4];
#pragma unroll
        for (int i = 0; i < 16; i++)
#pragma unroll
            for (int j = 0; j < 4; j++) acc[i][j] = 0.f;

#pragma unroll
        for (int nt = 0; nt < 16; nt++) {
#pragma unroll
            for (int ks = 0; ks < 4; ks++) {
                u32 off = (u32)((nt * 8 + brow) * LDQK + ks * 32 + bcol);
                u32 b0, b1, c0, c1;
                ldsm2(sKH + off, b0, b1);
                ldsm2(sKL + off, c0, c1);
                mma16816(acc[nt], qh[ks][0], qh[ks][1], qh[ks][2], qh[ks][3], b0, b1);
                mma16816(acc[nt], qh[ks][0], qh[ks][1], qh[ks][2], qh[ks][3], c0, c1);
                mma16816(acc[nt], ql[ks][0], ql[ks][1], ql[ks][2], ql[ks][3], b0, b1);
            }
        }

        float tm0 = -1e30f, tm1 = -1e30f;
#pragma unroll
        for (int nt = 0; nt < 16; nt++) {
            tm0 = fmaxf(tm0, fmaxf(acc[nt][0], acc[nt][1]));
            tm1 = fmaxf(tm1, fmaxf(acc[nt][2], acc[nt][3]));
        }
        tm0 = fmaxf(tm0, __shfl_xor_sync(0xffffffffu, tm0, 1));
        tm0 = fmaxf(tm0, __shfl_xor_sync(0xffffffffu, tm0, 2));
        tm1 = fmaxf(tm1, __shfl_xor_sync(0xffffffffu, tm1, 1));
        tm1 = fmaxf(tm1, __shfl_xor_sync(0xffffffffu, tm1, 2));
        float mn0 = fmaxf(m0, tm0), mn1 = fmaxf(m1, tm1);
        float a0 = __expf(m0 - mn0), a1 = __expf(m1 - mn1);
        m0 = mn0;
        m1 = mn1;
        float s0 = 0.f, s1 = 0.f;
#pragma unroll
        for (int nt = 0; nt < 16; nt++) {
            acc[nt][0] = __expf(acc[nt][0] - m0);
            acc[nt][1] = __expf(acc[nt][1] - m0);
            acc[nt][2] = __expf(acc[nt][2] - m1);
            acc[nt][3] = __expf(acc[nt][3] - m1);
            s0 += acc[nt][0] + acc[nt][1];
            s1 += acc[nt][2] + acc[nt][3];
        }
        s0 += __shfl_xor_sync(0xffffffffu, s0, 1);
        s0 += __shfl_xor_sync(0xffffffffu, s0, 2);
        s1 += __shfl_xor_sync(0xffffffffu, s1, 1);
        s1 += __shfl_xor_sync(0xffffffffu, s1, 2);
        l0 = l0 * a0 + s0;
        l1 = l1 * a1 + s1;
#pragma unroll
        for (int on = 0; on < 8; on++) {
            accO[on][0] *= a0;
            accO[on][1] *= a0;
            accO[on][2] *= a1;
            accO[on][3] *= a1;
        }

#pragma unroll
        for (int ks = 0; ks < 8; ks++) {
            u32 ah[4], al[4];
            split2(acc[2 * ks][0], acc[2 * ks][1], ah[0], al[0]);
            split2(acc[2 * ks][2], acc[2 * ks][3], ah[1], al[1]);
            split2(acc[2 * ks + 1][0], acc[2 * ks + 1][1], ah[2], al[2]);
            split2(acc[2 * ks + 1][2], acc[2 * ks + 1][3], ah[3], al[3]);
#pragma unroll
            for (int on = 0; on < 8; on++) {
                u32 off = (u32)((on * 8 + brow) * LDV + ks * 32 + bcol);
                u32 b0, b1, c0, c1;
                ldsm2(sVH + off, b0, b1);
                ldsm2(sVL + off, c0, c1);
                mma16816(accO[on], ah[0], ah[1], ah[2], ah[3], b0, b1);
                mma16816(accO[on], ah[0], ah[1], ah[2], ah[3], c0, c1);
                mma16816(accO[on], al[0], al[1], al[2], al[3], b0, b1);
            }
        }
        __syncthreads();
        if (t + 2 < NTILE) kv_prefetch(t + 2, t & 1);
    }

    float i0 = 1.0f / l0, i1 = 1.0f / l1;
    int t0 = qt * 128 + wid * 16 + (lane >> 2);
    size_t base0 = ((size_t)b * SEQ + t0) * DIM + h * HDIM;
    size_t base1 = ((size_t)b * SEQ + t0 + 8) * DIM + h * HDIM;
#pragma unroll
    for (int on = 0; on < 8; on++) {
        int d = on * 8 + (lane & 3) * 2;
        u32 hi, lo;
        split2(accO[on][0] * i0, accO[on][1] * i0, hi, lo);
        *reinterpret_cast<u32*>(och + base0 + d) = hi;
        *reinterpret_cast<u32*>(ocl + base0 + d) = lo;
        split2(accO[on][2] * i1, accO[on][3] * i1, hi, lo);
        *reinterpret_cast<u32*>(och + base1 + d) = hi;
        *reinterpret_cast<u32*>(ocl + base1 + d) = lo;
    }
}

// ---------------- warp-MMA GEMM, pre-split bf16 operands, BK=16 (best known) ----------------
struct PB3 { const bf16* p0; const bf16* p1; const bf16* p2; };

constexpr int GLDB = 48;
constexpr int GPLANE = 128 * GLDB;
constexpr int GSBUF = 4 * GPLANE;
constexpr int GSMEM = 2 * GSBUF;

__global__ void __launch_bounds__(128, 2)
gemm_mma_kernel(const bf16* __restrict__ Ah, PB3 BW,
                float* __restrict__ C, const float* __restrict__ R,
                int N, int K, size_t sCz, size_t aLoD, size_t bLoD) {
    extern __shared__ __align__(16) char smem[];
    const int tid = threadIdx.x;
    const int lane = tid & 31, wid = tid >> 5;
    const int wy = wid >> 1, wx = wid & 1;
    const u32 sbase = smem_u32(smem);

    const bf16* Bh = (blockIdx.z == 0) ? BW.p0 : (blockIdx.z == 1) ? BW.p1 : BW.p2;
    const bf16* Ab = Ah + (size_t)(blockIdx.y * 128) * K;
    const bf16* Bb = Bh + (size_t)(blockIdx.x * 128) * K;

    float acc[4][8][4];
#pragma unroll
    for (int i = 0; i < 4; i++)
#pragma unroll
        for (int j = 0; j < 8; j++)
#pragma unroll
            for (int q = 0; q < 4; q++) acc[i][j][q] = 0.f;

    const int nchunk = K >> 4;

    auto prefetch = [&](int c, int buf) {
        u32 sb = sbase + (u32)(buf * GSBUF);
        const bf16* Asrc = Ab + c * 16;
        const bf16* Bsrc = Bb + c * 16;
#pragma unroll
        for (int i = 0; i < 8; i++) {
            int idx = tid + i * 128;
            int plane = idx >> 8;
            int rem = idx & 255;
            int row = rem >> 1, hf = rem & 1;
            const bf16* src;
            if (plane == 0)      src = Asrc + (size_t)row * K + hf * 8;
            else if (plane == 1) src = Asrc + aLoD + (size_t)row * K + hf * 8;
            else if (plane == 2) src = Bsrc + (size_t)row * K + hf * 8;
            else                 src = Bsrc + bLoD + (size_t)row * K + hf * 8;
            cp16(sb + plane * GPLANE + row * GLDB + hf * 16, src);
        }
        cp_commit();
    };

    prefetch(0, 0);
    prefetch(1, 1);

    const int arow = wy * 64 + (lane & 15);
    const int acol = ((lane >> 4) & 1) * 16;
    const int brow0 = wx * 64 + (lane & 7);
    const int bcol = ((lane >> 3) & 1) * 16;

    for (int c = 0; c < nchunk; ++c) {
        if (c == nchunk - 1) cp_wait0(); else cp_wait1();
        __syncthreads();

        {
            u32 base = sbase + (u32)((c & 1) * GSBUF);
            u32 aH = base, aL = base + GPLANE;
            u32 bH = base + 2 * GPLANE, bL = base + 3 * GPLANE;

            u32 ah[4][4], al[4][4];
#pragma unroll
            for (int mt = 0; mt < 4; ++mt) {
                u32 off = (u32)((arow + mt * 16) * GLDB + acol);
                ldsm4(aH + off, ah[mt][0], ah[mt][1], ah[mt][2], ah[mt][3]);
                ldsm4(aL + off, al[mt][0], al[mt][1], al[mt][2], al[mt][3]);
            }
#pragma unroll
            for (int g = 0; g < 2; ++g) {
                u32 bh[4][2], bl[4][2];
#pragma unroll
                for (int nt = 0; nt < 4; ++nt) {
                    u32 off = (u32)((brow0 + (g * 4 + nt) * 8) * GLDB + bcol);
                    ldsm2(bH + off, bh[nt][0], bh[nt][1]);
                    ldsm2(bL + off, bl[nt][0], bl[nt][1]);
                }
#pragma unroll
                for (int mt = 0; mt < 4; ++mt)
#pragma unroll
                    for (int nt = 0; nt < 4; ++nt) {
                        float* a = acc[mt][g * 4 + nt];
                        mma16816(a, ah[mt][0], ah[mt][1], ah[mt][2], ah[mt][3],
                                 bh[nt][0], bh[nt][1]);
                        mma16816(a, ah[mt][0], ah[mt][1], ah[mt][2], ah[mt][3],
                                 bl[nt][0], bl[nt][1]);
                        mma16816(a, al[mt][0], al[mt][1], al[mt][2], al[mt][3],
                                 bh[nt][0], bh[nt][1]);
                    }
            }
        }
        __syncthreads();
        if (c + 2 < nchunk) prefetch(c + 2, c & 1);
    }

    float* Cz = C + (size_t)blockIdx.z * sCz;
    const float* Rz = R;
#pragma unroll
    for (int mt = 0; mt < 4; ++mt) {
        int row0 = blockIdx.y * 128 + wy * 64 + mt * 16 + (lane >> 2);
#pragma unroll
        for (int nt = 0; nt < 8; ++nt) {
            int col = blockIdx.x * 128 + wx * 64 + nt * 8 + (lane & 3) * 2;
            size_t o0 = (size_t)row0 * N + col;
            size_t o1 = (size_t)(row0 + 8) * N + col;
            float2 v0 = make_float2(acc[mt][nt][0], acc[mt][nt][1]);
            float2 v1 = make_float2(acc[mt][nt][2], acc[mt][nt][3]);
            if (Rz) {
                float2 r0 = *reinterpret_cast<const float2*>(Rz + o0);
                float2 r1 = *reinterpret_cast<const float2*>(Rz + o1);
                v0.x += r0.x; v0.y += r0.y;
                v1.x += r1.x; v1.y += r1.y;
            }
            *reinterpret_cast<float2*>(Cz + o0) = v0;
            *reinterpret_cast<float2*>(Cz + o1) = v1;
        }
    }
}

// ---------------- fused W1/W3 GEMM with swiglu epilogue (BK=16) ----------------
constexpr int WLDB  = 48;
constexpr int WAPL  = 128 * WLDB;
constexpr int WBPL  = 64 * WLDB;
constexpr int WSBUF = 2 * WAPL + 4 * WBPL;
constexpr int WSMEM = 2 * WSBUF;

__global__ void __launch_bounds__(128, 2)
gemm_w13_kernel(const bf16* __restrict__ Ah,
                const bf16* __restrict__ W1h, const bf16* __restrict__ W3h,
                bf16* __restrict__ gh, bf16* __restrict__ gl,
                int K, size_t aLoD, size_t bLoD) {
    extern __shared__ __align__(16) char smem[];
    const int tid = threadIdx.x;
    const int lane = tid & 31, wid = tid >> 5;
    const int wy = wid >> 1, wx = wid & 1;
    const u32 sbase = smem_u32(smem);

    const bf16* Ab = Ah + (size_t)(blockIdx.y * 128) * K;
    const bf16* B1 = W1h + (size_t)(blockIdx.x * 64) * K;
    const bf16* B3 = W3h + (size_t)(blockIdx.x * 64) * K;

    float acc1[4][4][4], acc3[4][4][4];
#pragma unroll
    for (int i = 0; i < 4; i++)
#pragma unroll
        for (int j = 0; j < 4; j++)
#pragma unroll
            for (int q = 0; q < 4; q++) { acc1[i][j][q] = 0.f; acc3[i][j][q] = 0.f; }

    const int nchunk = K >> 4;

    auto prefetch = [&](int c, int buf) {
        u32 sb = sbase + (u32)(buf * WSBUF);
        const bf16* Asrc = Ab + c * 16;
        const bf16* B1s = B1 + c * 16;
        const bf16* B3s = B3 + c * 16;
#pragma unroll
        for (int i = 0; i < 8; i++) {
            int idx = tid + i * 128;
            if (idx < 512) {
                int plane = idx >> 8;
                int rem = idx & 255;
                int row = rem >> 1, hf = rem & 1;
                const bf16* src = Asrc + (plane ? aLoD : 0) + (size_t)row * K + hf * 8;
                cp16(sb + plane * WAPL + row * WLDB + hf * 16, src);
            } else {
                int bidx = idx - 512;
                int plane = bidx >> 7;
                int rem = bidx & 127;
                int row = rem >> 1, hf = rem & 1;
                const bf16* src;
                if (plane == 0)      src = B1s + (size_t)row * K + hf * 8;
                else if (plane == 1) src = B1s + bLoD + (size_t)row * K + hf * 8;
                else if (plane == 2) src = B3s + (size_t)row * K + hf * 8;
                else                 src = B3s + bLoD + (size_t)row * K + hf * 8;
                cp16(sb + 2 * WAPL + plane * WBPL + row * WLDB + hf * 16, src);
            }
        }
        cp_commit();
    };

    prefetch(0, 0);
    prefetch(1, 1);

    const int arow = wy * 64 + (lane & 15);
    const int acol = ((lane >> 4) & 1) * 16;
    const int brow = wx * 32 + (lane & 7);
    const int bcol = ((lane >> 3) & 1) * 16;

    for (int c = 0; c < nchunk; ++c) {
        if (c == nchunk - 1) cp_wait0(); else cp_wait1();
        __syncthreads();

        {
            u32 base = sbase + (u32)((c & 1) * WSBUF);
            u32 aH = base, aL = base + WAPL;
            u32 b1H = base + 2 * WAPL;
            u32 b1L = b1H + WBPL;
            u32 b3H = b1L + WBPL;
            u32 b3L = b3H + WBPL;

            u32 ah[4][4], al[4][4];
#pragma unroll
            for (int mt = 0; mt < 4; ++mt) {
                u32 off = (u32)((arow + mt * 16) * WLDB + acol);
                ldsm4(aH + off, ah[mt][0], ah[mt][1], ah[mt][2], ah[mt][3]);
                ldsm4(aL + off, al[mt][0], al[mt][1], al[mt][2], al[mt][3]);
            }
            {
                u32 bh[4][2], bl[4][2];
#pragma unroll
                for (int nt = 0; nt < 4; ++nt) {
                    u32 off = (u32)((brow + nt * 8) * WLDB + bcol);
                    ldsm2(b1H + off, bh[nt][0], bh[nt][1]);
                    ldsm2(b1L + off, bl[nt][0], bl[nt][1]);
                }
#pragma unroll
                for (int mt = 0; mt < 4; ++mt)
#pragma unroll
                    for (int nt = 0; nt < 4; ++nt) {
                        float* a = acc1[mt][nt];
                        mma16816(a, ah[mt][0], ah[mt][1], ah[mt][2], ah[mt][3],
                                 bh[nt][0], bh[nt][1]);
                        mma16816(a, ah[mt][0], ah[mt][1], ah[mt][2], ah[mt][3],
                                 bl[nt][0], bl[nt][1]);
                        mma16816(a, al[mt][0], al[mt][1], al[mt][2], al[mt][3],
                                 bh[nt][0], bh[nt][1]);
                    }
            }
            {
                u32 bh[4][2], bl[4][2];
#pragma unroll
                for (int nt = 0; nt < 4; ++nt) {
                    u32 off = (u32)((brow + nt * 8) * WLDB + bcol);
                    ldsm2(b3H + off, bh[nt][0], bh[nt][1]);
                    ldsm2(b3L + off, bl[nt][0], bl[nt][1]);
                }
#pragma unroll
                for (int mt = 0; mt < 4; ++mt)
#pragma unroll
                    for (int nt = 0; nt < 4; ++nt) {
                        float* a = acc3[mt][nt];
                        mma16816(a, ah[mt][0], ah[mt][1], ah[mt][2], ah[mt][3],
                                 bh[nt][0], bh[nt][1]);
                        mma16816(a, ah[mt][0], ah[mt][1], ah[mt][2], ah[mt][3],
                                 bl[nt][0], bl[nt][1]);
                        mma16816(a, al[mt][0], al[mt][1], al[mt][2], al[mt][3],
                                 bh[nt][0], bh[nt][1]);
                    }
            }
        }
        __syncthreads();
        if (c + 2 < nchunk) prefetch(c + 2, c & 1);
    }

#pragma unroll
    for (int mt = 0; mt < 4; ++mt) {
        int row0 = blockIdx.y * 128 + wy * 64 + mt * 16 + (lane >> 2);
#pragma unroll
        for (int nt = 0; nt < 4; ++nt) {
            int col = blockIdx.x * 64 + wx * 32 + nt * 8 + (lane & 3) * 2;
            size_t o0 = (size_t)row0 * FFDIM + col;
            size_t o1 = (size_t)(row0 + 8) * FFDIM + col;
            float a0 = acc1[mt][nt][0], a1 = acc1[mt][nt][1];
            float a2 = acc1[mt][nt][2], a3 = acc1[mt][nt][3];
            float g0 = a0 / (1.0f + __expf(-a0)) * acc3[mt][nt][0];
            float g1 = a1 / (1.0f + __expf(-a1)) * acc3[mt][nt][1];
            float g2 = a2 / (1.0f + __expf(-a2)) * acc3[mt][nt][2];
            float g3 = a3 / (1.0f + __expf(-a3)) * acc3[mt][nt][3];
            u32 hi, lo;
            split2(g0, g1, hi, lo);
            *reinterpret_cast<u32*>(gh + o0) = hi;
            *reinterpret_cast<u32*>(gl + o0) = lo;
            split2(g2, g3, hi, lo);
            *reinterpret_cast<u32*>(gh + o1) = hi;
            *reinterpret_cast<u32*>(gl + o1) = lo;
        }
    }
}

// ---------------- host ----------------
extern "C" void kernel_launch(void* const* d_in, const int* in_sizes, int n_in,
                              void* d_out, int out_size) {
    const int*   tokens       = (const int*)d_in[0];
    const float* embed        = (const float*)d_in[1];
    const float* attn_norm_w  = (const float*)d_in[2];
    const float* wq           = (const float*)d_in[3];
    const float* wk           = (const float*)d_in[4];
    const float* wv           = (const float*)d_in[5];
    const float* wo           = (const float*)d_in[6];
    const float* ffn_norm_w   = (const float*)d_in[7];
    const float* w1           = (const float*)d_in[8];
    const float* w2           = (const float*)d_in[9];
    const float* w3           = (const float*)d_in[10];
    const float* final_norm_w = (const float*)d_in[11];
    float* out = (float*)d_out;

    cudaFuncSetAttribute(gemm_mma_kernel,
                         cudaFuncAttributeMaxDynamicSharedMemorySize, GSMEM);
    cudaFuncSetAttribute(gemm_w13_kernel,
                         cudaFuncAttributeMaxDynamicSharedMemorySize, WSMEM);
    cudaFuncSetAttribute(flash_kernel,
                         cudaFuncAttributeMaxDynamicSharedMemorySize, FLASH_SMEM);

    float* buf = nullptr;
    cudaGetSymbolAddress((void**)&buf, g_buf);
    int* seg = nullptr;
    cudaGetSymbolAddress((void**)&seg, g_seg);
    bf16* ab = nullptr;
    cudaGetSymbolAddress((void**)&ab, g_abuf);
    bf16* ws = nullptr;
    cudaGetSymbolAddress((void**)&ws, g_wsplit);

    float* x    = buf + OFF_X;
    float* y    = buf + OFF_Y;
    float* qr   = buf + OFF_Q;
    float* kr   = buf + OFF_K;
    float* vr   = buf + OFF_V;
    float* hf   = buf + OFF_HF;
    float* ssum = buf + OFF_SSUM;
    float* scnt = buf + OFF_SCNT;
    float* cosT = buf + OFF_COS;
    float* sinT = buf + OFF_SIN;

    bf16* xnh = ab + BXN;
    bf16* och = ab + BOC;
    bf16* qph = ab + BQP;
    bf16* kph = ab + BKP;
    bf16* vth = ab + BVT;
    bf16* ggh = ab + BGG;

    WSrc wsrc{{wq, wk, wv, wo, w1, w3, w2}};
    wsplit_all_kernel<<<(int)((TOT4 + 255) / 256), 256>>>(wsrc, ws);

    embed_kernel<<<BT, 128>>>(tokens, embed, x);
    rope_table_kernel<<<(SEQ * HALFHD + 255) / 256, 256>>>(cosT, sinT);

    for (int l = 0; l < NLAYER; l++) {
        const bf16* wqh = ws + WQO + (size_t)l * DIM * DIM;
        const bf16* wkh = ws + WKO + (size_t)l * DIM * DIM;
        const bf16* wvh = ws + WVO + (size_t)l * DIM * DIM;
        const bf16* woh = ws + WOO + (size_t)l * DIM * DIM;
        const bf16* w1h = ws + W1O + (size_t)l * FFDIM * DIM;
        const bf16* w3h = ws + W3O + (size_t)l * FFDIM * DIM;
        const bf16* w2h = ws + W2O + (size_t)l * DIM * FFDIM;

        rmsnorm_bf16_kernel<<<BT / RPB, 128>>>(x, attn_norm_w + (size_t)l * DIM,
                                               xnh, xnh + NX);

        dim3 gqkv(DIM / 128, BT / 128, 3);
        gemm_mma_kernel<<<gqkv, 128, GSMEM>>>(xnh, PB3{wqh, wkh, wvh},
                                              qr, nullptr, DIM, DIM, NX, NX, NPROJ);

        prep_attn_kernel<<<PACK_BLOCKS + VT_BLOCKS, 256>>>(
            qr, kr, vr, cosT, sinT,
            qph, qph + NX, kph, kph + NX, vth, vth + NX);

        flash_kernel<<<dim3(SEQ / 128, BSZ * NHEAD), 256, FLASH_SMEM>>>(
            qph, qph + NX, kph, kph + NX, vth, vth + NX, och, och + NX);

        dim3 gproj(DIM / 128, BT / 128, 1);
        gemm_mma_kernel<<<gproj, 128, GSMEM>>>(och, PB3{woh, woh, woh},
                                               y, x, DIM, DIM, 0, NX, NPROJ);

        rmsnorm_bf16_kernel<<<BT / RPB, 128>>>(y, ffn_norm_w + (size_t)l * DIM,
                                               xnh, xnh + NX);

        dim3 g13(FFDIM / 64, BT / 128, 1);
        gemm_w13_kernel<<<g13, 128, WSMEM>>>(xnh, w1h, w3h, ggh, ggh + NHID,
                                             DIM, NX, NFF);

        gemm_mma_kernel<<<gproj, 128, GSMEM>>>(ggh, PB3{w2h, w2h, w2h},
                                               x, y, DIM, FFDIM, 0, NHID, NFF);
    }

    rmsnorm_f32_kernel<<<BT / RPB, 128>>>(x, final_norm_w, hf);

    segscan_kernel<<<BSZ, 256>>>(tokens, seg);
    zero_kernel<<<4096, 256>>>(ssum, NSEGS + NSEGC);
    segsum_kernel<<<BT, 128>>>(hf, seg, ssum, scnt);
    pool_kernel<<<BT, 128>>>(hf, seg, ssum, scnt, out);
}

// round 15
// speedup vs baseline: 1.0707x; 1.0033x over previous
#include <cuda_runtime.h>
#include <cuda_bf16.h>
#include <math.h>

// Problem constants
#define BSZ 4
#define SEQ 2048
#define DIM 512
#define NHEAD 8
#define NLAYER 4
#define FFDIM 2048
#define HDIM 64
#define HALFHD 32
#define EPSV 1e-6f
#define ALPHAV 0.5f
#define LOG_ROPE_BASE 9.210340371976184   // ln(10000)

#define BT (BSZ * SEQ)                    // 8192

typedef unsigned int u32;
typedef unsigned long long u64;
typedef __nv_bfloat16 bf16;

// ---------------- scratch buffers ----------------
constexpr size_t NX    = (size_t)BT * DIM;
constexpr size_t NHID  = (size_t)BT * FFDIM;
constexpr size_t NSEGS = (size_t)BSZ * (SEQ + 1) * DIM;
constexpr size_t NSEGC = (size_t)BSZ * (SEQ + 1);
constexpr size_t NROPE = (size_t)SEQ * HALFHD;

constexpr size_t OFF_X    = 0;
constexpr size_t OFF_Y    = OFF_X  + NX;
constexpr size_t OFF_Q    = OFF_Y  + NX;   // qr,kr,vr contiguous (fused QKV)
constexpr size_t OFF_K    = OFF_Q  + NX;
constexpr size_t OFF_V    = OFF_K  + NX;
constexpr size_t OFF_HF   = OFF_V  + NX;
constexpr size_t OFF_SSUM = OFF_HF + NX;
constexpr size_t OFF_SCNT = OFF_SSUM + NSEGS;
constexpr size_t OFF_COS  = OFF_SCNT + NSEGC;
constexpr size_t OFF_SIN  = OFF_COS + NROPE;
constexpr size_t TOTALF   = OFF_SIN + NROPE;

__device__ float g_buf[TOTALF];
__device__ int   g_seg[BT];

// bf16 activation planes (hi plane, then lo plane at +delta)
constexpr size_t BXN = 0;
constexpr size_t BOC = 2 * NX;
constexpr size_t BQP = 4 * NX;
constexpr size_t BKP = 6 * NX;
constexpr size_t BVT = 8 * NX;
constexpr size_t BGG = 10 * NX;
constexpr size_t TOTALB = 10 * NX + 2 * NHID;
__device__ bf16 g_abuf[TOTALB];

// bf16 split weights
constexpr size_t NPROJ = (size_t)NLAYER * DIM * DIM;
constexpr size_t NFF   = (size_t)NLAYER * FFDIM * DIM;
constexpr size_t WQO = 0;
constexpr size_t WKO = 2 * NPROJ;
constexpr size_t WVO = 4 * NPROJ;
constexpr size_t WOO = 6 * NPROJ;
constexpr size_t W1O = 8 * NPROJ;
constexpr size_t W3O = W1O + 2 * NFF;
constexpr size_t W2O = W3O + 2 * NFF;
constexpr size_t TOTALW = W2O + 2 * NFF;
__device__ bf16 g_wsplit[TOTALW];

// ---------------- PTX helpers ----------------
__device__ __forceinline__ u32 smem_u32(const void* p) {
    u32 a;
    asm("{ .reg .u64 t; cvta.to.shared.u64 t, %1; cvt.u32.u64 %0, t; }" : "=r"(a) : "l"(p));
    return a;
}
__device__ __forceinline__ void ldsm4(u32 addr, u32& r0, u32& r1, u32& r2, u32& r3) {
    asm volatile("ldmatrix.sync.aligned.m8n8.x4.shared.b16 {%0,%1,%2,%3}, [%4];"
                 : "=r"(r0), "=r"(r1), "=r"(r2), "=r"(r3) : "r"(addr));
}
__device__ __forceinline__ void ldsm2(u32 addr, u32& r0, u32& r1) {
    asm volatile("ldmatrix.sync.aligned.m8n8.x2.shared.b16 {%0,%1}, [%2];"
                 : "=r"(r0), "=r"(r1) : "r"(addr));
}
__device__ __forceinline__ void mma16816(float* d, u32 a0, u32 a1, u32 a2, u32 a3,
                                         u32 b0, u32 b1) {
    asm volatile(
        "mma.sync.aligned.m16n8k16.row.col.f32.bf16.bf16.f32 "
        "{%0,%1,%2,%3}, {%4,%5,%6,%7}, {%8,%9}, {%0,%1,%2,%3};"
        : "+f"(d[0]), "+f"(d[1]), "+f"(d[2]), "+f"(d[3])
        : "r"(a0), "r"(a1), "r"(a2), "r"(a3), "r"(b0), "r"(b1));
}
__device__ __forceinline__ void cp16(u32 dst, const void* src) {
    asm volatile("cp.async.cg.shared.global [%0], [%1], 16;" :: "r"(dst), "l"(src));
}
__device__ __forceinline__ void cp_commit() { asm volatile("cp.async.commit_group;"); }
__device__ __forceinline__ void cp_wait0()  { asm volatile("cp.async.wait_group 0;" ::: "memory"); }
__device__ __forceinline__ void cp_wait1()  { asm volatile("cp.async.wait_group 1;" ::: "memory"); }

__device__ __forceinline__ void split_pack(float4 v, uint2& hp, uint2& lp) {
    __nv_bfloat162 h01, h23, l01, l23;
    h01.x = __float2bfloat16_rn(v.x);
    h01.y = __float2bfloat16_rn(v.y);
    h23.x = __float2bfloat16_rn(v.z);
    h23.y = __float2bfloat16_rn(v.w);
    l01.x = __float2bfloat16_rn(v.x - __bfloat162float(h01.x));
    l01.y = __float2bfloat16_rn(v.y - __bfloat162float(h01.y));
    l23.x = __float2bfloat16_rn(v.z - __bfloat162float(h23.x));
    l23.y = __float2bfloat16_rn(v.w - __bfloat162float(h23.y));
    hp.x = *reinterpret_cast<u32*>(&h01);
    hp.y = *reinterpret_cast<u32*>(&h23);
    lp.x = *reinterpret_cast<u32*>(&l01);
    lp.y = *reinterpret_cast<u32*>(&l23);
}
__device__ __forceinline__ void split2(float x, float y, u32& hi, u32& lo) {
    __nv_bfloat162 h, l;
    h.x = __float2bfloat16_rn(x);
    h.y = __float2bfloat16_rn(y);
    l.x = __float2bfloat16_rn(x - __bfloat162float(h.x));
    l.y = __float2bfloat16_rn(y - __bfloat162float(h.y));
    hi = *reinterpret_cast<u32*>(&h);
    lo = *reinterpret_cast<u32*>(&l);
}

__device__ __forceinline__ bool is_sep(int c) {
    switch (c) {
        case 9: case 10: case 13: case 32: case 33: case 34: case 35: case 36:
        case 37: case 38: case 39: case 40: case 41: case 42: case 43: case 44:
        case 45: case 46: case 47: case 58: case 59: case 60: case 61: case 62:
        case 63: case 64: case 91: case 92: case 93: case 94: case 123:
        case 124: case 125: case 126:
            return true;
        default:
            return false;
    }
}

// ---------------- small kernels ----------------
struct WSrc { const float* s[7]; };
constexpr size_t P4 = NPROJ / 4;
constexpr size_t F4 = NFF / 4;
constexpr size_t TOT4 = 4 * P4 + 3 * F4;

__global__ void wsplit_all_kernel(WSrc src, bf16* __restrict__ ws) {
    size_t i4 = (size_t)blockIdx.x * blockDim.x + threadIdx.x;
    if (i4 >= TOT4) return;
    int r;
    size_t local;
    bf16 *hi, *lo;
    const float* s;
    if (i4 < 4 * P4) {
        r = (int)(i4 / P4);
        local = i4 - (size_t)r * P4;
        s = src.s[r];
        hi = ws + (size_t)r * 2 * NPROJ;
        lo = hi + NPROJ;
    } else {
        size_t j = i4 - 4 * P4;
        r = (int)(j / F4);
        local = j - (size_t)r * F4;
        s = src.s[4 + r];
        hi = ws + W1O + (size_t)r * 2 * NFF;
        lo = hi + NFF;
    }
    float4 v = reinterpret_cast<const float4*>(s)[local];
    uint2 hp, lp;
    split_pack(v, hp, lp);
    *reinterpret_cast<uint2*>(hi + local * 4) = hp;
    *reinterpret_cast<uint2*>(lo + local * 4) = lp;
}

__global__ void embed_kernel(const int* __restrict__ tokens,
                             const float* __restrict__ embed,
                             float* __restrict__ x) {
    int m = blockIdx.x;
    int tok = tokens[m];
    tok = min(max(tok, 0), 255);
    reinterpret_cast<float4*>(x + (size_t)m * DIM)[threadIdx.x] =
        reinterpret_cast<const float4*>(embed + (size_t)tok * DIM)[threadIdx.x];
}

// rmsnorm, warp-per-row (sync-free): 256 thr = 8 warps = 8 rows/block
__global__ void rmsnorm_bf16_kernel(const float* __restrict__ x,
                                    const float* __restrict__ w,
                                    bf16* __restrict__ oh, bf16* __restrict__ ol) {
    int wid = threadIdx.x >> 5, lane = threadIdx.x & 31;
    int row = blockIdx.x * 8 + wid;
    const float4* xr = reinterpret_cast<const float4*>(x + (size_t)row * DIM);
    float4 v[4];
    float ss = 0.f;
#pragma unroll
    for (int i = 0; i < 4; i++) {
        v[i] = xr[lane + i * 32];
        ss += v[i].x * v[i].x + v[i].y * v[i].y + v[i].z * v[i].z + v[i].w * v[i].w;
    }
    for (int s = 16; s; s >>= 1) ss += __shfl_xor_sync(0xffffffffu, ss, s);
    float rs = rsqrtf(ss * (1.0f / DIM) + EPSV);
#pragma unroll
    for (int i = 0; i < 4; i++) {
        float4 wv = reinterpret_cast<const float4*>(w)[lane + i * 32];
        float4 r = make_float4(v[i].x * rs * wv.x, v[i].y * rs * wv.y,
                               v[i].z * rs * wv.z, v[i].w * rs * wv.w);
        uint2 hp, lp;
        split_pack(r, hp, lp);
        size_t o = (size_t)row * DIM + (lane + i * 32) * 4;
        *reinterpret_cast<uint2*>(oh + o) = hp;
        *reinterpret_cast<uint2*>(ol + o) = lp;
    }
}

__global__ void rmsnorm_f32_kernel(const float* __restrict__ x,
                                   const float* __restrict__ w,
                                   float* __restrict__ o) {
    int wid = threadIdx.x >> 5, lane = threadIdx.x & 31;
    int row = blockIdx.x * 8 + wid;
    const float4* xr = reinterpret_cast<const float4*>(x + (size_t)row * DIM);
    float4 v[4];
    float ss = 0.f;
#pragma unroll
    for (int i = 0; i < 4; i++) {
        v[i] = xr[lane + i * 32];
        ss += v[i].x * v[i].x + v[i].y * v[i].y + v[i].z * v[i].z + v[i].w * v[i].w;
    }
    for (int s = 16; s; s >>= 1) ss += __shfl_xor_sync(0xffffffffu, ss, s);
    float rs = rsqrtf(ss * (1.0f / DIM) + EPSV);
#pragma unroll
    for (int i = 0; i < 4; i++) {
        float4 wv = reinterpret_cast<const float4*>(w)[lane + i * 32];
        float4 r = make_float4(v[i].x * rs * wv.x, v[i].y * rs * wv.y,
                               v[i].z * rs * wv.z, v[i].w * rs * wv.w);
        reinterpret_cast<float4*>(o + (size_t)row * DIM)[lane + i * 32] = r;
    }
}

__global__ void rope_table_kernel(float* __restrict__ cosT, float* __restrict__ sinT) {
    int idx = blockIdx.x * blockDim.x + threadIdx.x;
    if (idx >= SEQ * HALFHD) return;
    int t = idx / HALFHD, i = idx % HALFHD;
    double inv = exp(-(double)i * (LOG_ROPE_BASE / (double)HALFHD));
    double ang = (double)t * inv;
    double s, c;
    sincos(ang, &s, &c);
    cosT[idx] = (float)c;
    sinT[idx] = (float)s;
}

constexpr int PACK_BLOCKS = (BSZ * NHEAD * SEQ * HALFHD) / 256;  // 2048
constexpr int VT_BLOCKS   = (SEQ / 32) * (HDIM / 32) * (BSZ * NHEAD); // 4096

__global__ void prep_attn_kernel(const float* __restrict__ qr,
                                 const float* __restrict__ kr,
                                 const float* __restrict__ vr,
                                 const float* __restrict__ cosT,
                                 const float* __restrict__ sinT,
                                 bf16* __restrict__ qph, bf16* __restrict__ qpl,
                                 bf16* __restrict__ kph, bf16* __restrict__ kpl,
                                 bf16* __restrict__ vth, bf16* __restrict__ vtl) {
    int tid = threadIdx.x;
    if (blockIdx.x < PACK_BLOCKS) {
        int gid = blockIdx.x * 256 + tid;
        int i = gid % HALFHD;
        int t = (gid / HALFHD) % SEQ;
        int h = (gid / (HALFHD * SEQ)) % NHEAD;
        int b = gid / (HALFHD * SEQ * NHEAD);
        size_t src = ((size_t)b * SEQ + t) * DIM + h * HDIM + 2 * i;
        size_t dst = (((size_t)(b * NHEAD + h)) * SEQ + t) * HDIM + 2 * i;
        float c = cosT[t * HALFHD + i];
        float s = sinT[t * HALFHD + i];
        float2 q2 = *reinterpret_cast<const float2*>(qr + src);
        float2 k2 = *reinterpret_cast<const float2*>(kr + src);
        const float qs = 0.125f;
        u32 hi, lo;
        split2((q2.x * c - q2.y * s) * qs, (q2.x * s + q2.y * c) * qs, hi, lo);
        *reinterpret_cast<u32*>(qph + dst) = hi;
        *reinterpret_cast<u32*>(qpl + dst) = lo;
        split2(k2.x * c - k2.y * s, k2.x * s + k2.y * c, hi, lo);
        *reinterpret_cast<u32*>(kph + dst) = hi;
        *reinterpret_cast<u32*>(kpl + dst) = lo;
    } else {
        __shared__ float smem_t[32][33];
        int bid = blockIdx.x - PACK_BLOCKS;
        int t0 = (bid & 63) * 32;
        int d0 = ((bid >> 6) & 1) * 32;
        int bh = bid >> 7;
        int b = bh >> 3, h = bh & 7;
        int tx = tid & 31, ty = tid >> 5;
#pragma unroll
        for (int r = 0; r < 32; r += 8)
            smem_t[ty + r][tx] =
                vr[((size_t)(b * SEQ) + t0 + ty + r) * DIM + h * HDIM + d0 + tx];
        __syncthreads();
#pragma unroll
        for (int r = 0; r < 32; r += 8) {
            float v = smem_t[tx][ty + r];
            bf16 hv = __float2bfloat16_rn(v);
            size_t o = ((size_t)bh * HDIM + d0 + ty + r) * SEQ + t0 + tx;
            vth[o] = hv;
            vtl[o] = __float2bfloat16_rn(v - __bfloat162float(hv));
        }
    }
}

__global__ void zero_kernel(float* __restrict__ p, size_t n) {
    size_t i = (size_t)blockIdx.x * blockDim.x + threadIdx.x;
    size_t stride = (size_t)gridDim.x * blockDim.x;
    for (; i < n; i += stride) p[i] = 0.0f;
}

__global__ void segscan_kernel(const int* __restrict__ tokens, int* __restrict__ seg) {
    int b = blockIdx.x;
    constexpr int PT = SEQ / 256;
    int flags[PT];
    int s = 0;
#pragma unroll
    for (int j = 0; j < PT; j++) {
        int tok = tokens[b * SEQ + threadIdx.x * PT + j];
        tok = min(max(tok, 0), 255);
        flags[j] = is_sep(tok) ? 1 : 0;
        s += flags[j];
    }
    __shared__ int wsum[8];
    int lane = threadIdx.x & 31, wp = threadIdx.x >> 5;
    int ps = s;
    for (int o = 1; o < 32; o <<= 1) {
        int v = __shfl_up_sync(0xffffffffu, ps, o);
        if (lane >= o) ps += v;
    }
    if (lane == 31) wsum[wp] = ps;
    __syncthreads();
    int woff = 0;
    for (int i = 0; i < wp; i++) woff += wsum[i];
    int run = ps - s + woff;
#pragma unroll
    for (int j = 0; j < PT; j++) {
        run += flags[j];
        seg[b * SEQ + threadIdx.x * PT + j] = run + b * (SEQ + 1);
    }
}

__global__ void segsum_kernel(const float* __restrict__ h, const int* __restrict__ seg,
                              float* __restrict__ ssum, float* __restrict__ scnt) {
    int m = blockIdx.x;
    int s = seg[m];
    float4 v = reinterpret_cast<const float4*>(h + (size_t)m * DIM)[threadIdx.x];
    float* base = ssum + (size_t)s * DIM + threadIdx.x * 4;
    atomicAdd(base + 0, v.x);
    atomicAdd(base + 1, v.y);
    atomicAdd(base + 2, v.z);
    atomicAdd(base + 3, v.w);
    if (threadIdx.x == 0) atomicAdd(scnt + s, 1.0f);
}

__global__ void pool_kernel(const float* __restrict__ h, const int* __restrict__ seg,
                            const float* __restrict__ ssum, const float* __restrict__ scnt,
                            float* __restrict__ out) {
    int m = blockIdx.x;
    int s = seg[m];
    float inv = 1.0f / fmaxf(scnt[s], 1.0f);
    float4 v = reinterpret_cast<const float4*>(h + (size_t)m * DIM)[threadIdx.x];
    float4 sm = reinterpret_cast<const float4*>(ssum + (size_t)s * DIM)[threadIdx.x];
    float4 r = make_float4(ALPHAV * v.x + (1.0f - ALPHAV) * sm.x * inv,
                           ALPHAV * v.y + (1.0f - ALPHAV) * sm.y * inv,
                           ALPHAV * v.z + (1.0f - ALPHAV) * sm.z * inv,
                           ALPHAV * v.w + (1.0f - ALPHAV) * sm.w * inv);
    reinterpret_cast<float4*>(out + (size_t)m * DIM)[threadIdx.x] = r;
}

// ---------------- fused flash attention (FT=128, pre-split, Q frags hoisted) ----------------
constexpr int FT = 128;
constexpr int LDQK = 144;
constexpr int LDV  = 272;
constexpr u32 SQH = 0;
constexpr u32 SQL = 18432;
constexpr u32 FKV0 = 36864;
constexpr u32 KPL = 18432;
constexpr u32 FVOFF = 36864;
constexpr u32 VPL = 17408;
constexpr u32 KVBUF = 71680;
constexpr int FLASH_SMEM = 36864 + 2 * 71680;  // 180224

__global__ void __launch_bounds__(256, 1)
flash_kernel(const bf16* __restrict__ qph, const bf16* __restrict__ qpl,
             const bf16* __restrict__ kph, const bf16* __restrict__ kpl,
             const bf16* __restrict__ vth, const bf16* __restrict__ vtl,
             bf16* __restrict__ och, bf16* __restrict__ ocl) {
    extern __shared__ __align__(16) char smem[];
    const u32 sb = smem_u32(smem);
    const int tid = threadIdx.x;
    const int lane = tid & 31, wid = tid >> 5;
    const int qt = blockIdx.x, bh = blockIdx.y;
    const int b = bh >> 3, h = bh & 7;

    const size_t qbase = ((size_t)bh * SEQ + qt * 128) * HDIM;
    const bf16* Kh = kph + (size_t)bh * SEQ * HDIM;
    const bf16* Kl = kpl + (size_t)bh * SEQ * HDIM;
    const bf16* Vh = vth + (size_t)bh * HDIM * SEQ;
    const bf16* Vl = vtl + (size_t)bh * HDIM * SEQ;

    auto kv_prefetch = [&](int tt, int buf) {
        u32 base = sb + FKV0 + (u32)buf * KVBUF;
#pragma unroll
        for (int i = 0; i < 8; i++) {
            int idx = tid + i * 256;
            int plane = idx >> 10;
            int rem = idx & 1023;
            int row = rem >> 3, hf = rem & 7;
            const bf16* src = (plane ? Kl : Kh) + (size_t)(tt * FT + row) * HDIM + hf * 8;
            cp16(base + plane * KPL + row * LDQK + hf * 16, src);
        }
#pragma unroll
        for (int i = 0; i < 8; i++) {
            int idx = tid + i * 256;
            int plane = idx >> 10;
            int rem = idx & 1023;
            int row = rem >> 4, hf = rem & 15;
            const bf16* src = (plane ? Vl : Vh) + (size_t)row * SEQ + tt * FT + hf * 8;
            cp16(base + FVOFF + plane * VPL + row * LDV + hf * 16, src);
        }
        cp_commit();
    };

#pragma unroll
    for (int i = 0; i < 8; i++) {
        int idx = tid + i * 256;
        int plane = idx >> 10;
        int rem = idx & 1023;
        int row = rem >> 3, hf = rem & 7;
        const bf16* src = (plane ? qpl : qph) + qbase + (size_t)row * HDIM + hf * 8;
        cp16(sb + (plane ? SQL : SQH) + row * LDQK + hf * 16, src);
    }
    kv_prefetch(0, 0);
    kv_prefetch(1, 1);

    float accO[8][4];
#pragma unroll
    for (int i = 0; i < 8; i++)
#pragma unroll
        for (int j = 0; j < 4; j++) accO[i][j] = 0.f;
    float m0 = -1e30f, m1 = -1e30f, l0 = 0.f, l1 = 0.f;

    const int arow = wid * 16 + (lane & 15);
    const int acol = ((lane >> 4) & 1) * 16;
    const int brow = lane & 7;
    const int bcol = ((lane >> 3) & 1) * 16;

    u32 qh[4][4], ql[4][4];

    constexpr int NTILE = SEQ / FT;
    for (int t = 0; t < NTILE; t++) {
        if (t == NTILE - 1) cp_wait0(); else cp_wait1();
        __syncthreads();

        if (t == 0) {
#pragma unroll
            for (int ks = 0; ks < 4; ks++) {
                u32 off = (u32)(arow * LDQK + ks * 32 + acol);
                ldsm4(sb + SQH + off, qh[ks][0], qh[ks][1], qh[ks][2], qh[ks][3]);
                ldsm4(sb + SQL + off, ql[ks][0], ql[ks][1], ql[ks][2], ql[ks][3]);
            }
        }

        const u32 kvb = sb + FKV0 + (u32)((t & 1) * KVBUF);
        const u32 sKH = kvb, sKL = kvb + KPL;
        const u32 sVH = kvb + FVOFF, sVL = kvb + FVOFF + VPL;

        float acc[16][4];
#pragma unroll
        for (int i = 0; i < 16; i++)
#pragma unroll
            for (int j = 0; j < 4; j++) acc[i][j] = 0.f;

#pragma unroll
        for (int nt = 0; nt < 16; nt++) {
#pragma unroll
            for (int ks = 0; ks < 4; ks++) {
                u32 off = (u32)((nt * 8 + brow) * LDQK + ks * 32 + bcol);
                u32 b0, b1, c0, c1;
                ldsm2(sKH + off, b0, b1);
                ldsm2(sKL + off, c0, c1);
                mma16816(acc[nt], qh[ks][0], qh[ks][1], qh[ks][2], qh[ks][3], b0, b1);
                mma16816(acc[nt], qh[ks][0], qh[ks][1], qh[ks][2], qh[ks][3], c0, c1);
                mma16816(acc[nt], ql[ks][0], ql[ks][1], ql[ks][2], ql[ks][3], b0, b1);
            }
        }

        float tm0 = -1e30f, tm1 = -1e30f;
#pragma unroll
        for (int nt = 0; nt < 16; nt++) {
            tm0 = fmaxf(tm0, fmaxf(acc[nt][0], acc[nt][1]));
            tm1 = fmaxf(tm1, fmaxf(acc[nt][2], acc[nt][3]));
        }
        tm0 = fmaxf(tm0, __shfl_xor_sync(0xffffffffu, tm0, 1));
        tm0 = fmaxf(tm0, __shfl_xor_sync(0xffffffffu, tm0, 2));
        tm1 = fmaxf(tm1, __shfl_xor_sync(0xffffffffu, tm1, 1));
        tm1 = fmaxf(tm1, __shfl_xor_sync(0xffffffffu, tm1, 2));
        float mn0 = fmaxf(m0, tm0), mn1 = fmaxf(m1, tm1);
        float a0 = __expf(m0 - mn0), a1 = __expf(m1 - mn1);
        m0 = mn0;
        m1 = mn1;
        float s0 = 0.f, s1 = 0.f;
#pragma unroll
        for (int nt = 0; nt < 16; nt++) {
            acc[nt][0] = __expf(acc[nt][0] - m0);
            acc[nt][1] = __expf(acc[nt][1] - m0);
            acc[nt][2] = __expf(acc[nt][2] - m1);
            acc[nt][3] = __expf(acc[nt][3] - m1);
            s0 += acc[nt][0] + acc[nt][1];
            s1 += acc[nt][2] + acc[nt][3];
        }
        s0 += __shfl_xor_sync(0xffffffffu, s0, 1);
        s0 += __shfl_xor_sync(0xffffffffu, s0, 2);
        s1 += __shfl_xor_sync(0xffffffffu, s1, 1);
        s1 += __shfl_xor_sync(0xffffffffu, s1, 2);
        l0 = l0 * a0 + s0;
        l1 = l1 * a1 + s1;
#pragma unroll
        for (int on = 0; on < 8; on++) {
            accO[on][0] *= a0;
            accO[on][1] *= a0;
            accO[on][2] *= a1;
            accO[on][3] *= a1;
        }

#pragma unroll
        for (int ks = 0; ks < 8; ks++) {
            u32 ah[4], al[4];
            split2(acc[2 * ks][0], acc[2 * ks][1], ah[0], al[0]);
            split2(acc[2 * ks][2], acc[2 * ks][3], ah[1], al[1]);
            split2(acc[2 * ks + 1][0], acc[2 * ks + 1][1], ah[2], al[2]);
            split2(acc[2 * ks + 1][2], acc[2 * ks + 1][3], ah[3], al[3]);
#pragma unroll
            for (int on = 0; on < 8; on++) {
                u32 off = (u32)((on * 8 + brow) * LDV + ks * 32 + bcol);
                u32 b0, b1, c0, c1;
                ldsm2(sVH + off, b0, b1);
                ldsm2(sVL + off, c0, c1);
                mma16816(accO[on], ah[0], ah[1], ah[2], ah[3], b0, b1);
                mma16816(accO[on], ah[0], ah[1], ah[2], ah[3], c0, c1);
                mma16816(accO[on], al[0], al[1], al[2], al[3], b0, b1);
            }
        }
        __syncthreads();
        if (t + 2 < NTILE) kv_prefetch(t + 2, t & 1);
    }

    float i0 = 1.0f / l0, i1 = 1.0f / l1;
    int t0 = qt * 128 + wid * 16 + (lane >> 2);
    size_t base0 = ((size_t)b * SEQ + t0) * DIM + h * HDIM;
    size_t base1 = ((size_t)b * SEQ + t0 + 8) * DIM + h * HDIM;
#pragma unroll
    for (int on = 0; on < 8; on++) {
        int d = on * 8 + (lane & 3) * 2;
        u32 hi, lo;
        split2(accO[on][0] * i0, accO[on][1] * i0, hi, lo);
        *reinterpret_cast<u32*>(och + base0 + d) = hi;
        *reinterpret_cast<u32*>(ocl + base0 + d) = lo;
        split2(accO[on][2] * i1, accO[on][3] * i1, hi, lo);
        *reinterpret_cast<u32*>(och + base1 + d) = hi;
        *reinterpret_cast<u32*>(ocl + base1 + d) = lo;
    }
}

// ---------------- warp-MMA GEMM, pre-split bf16 operands, BK=16 (best known) ----------------
struct PB3 { const bf16* p0; const bf16* p1; const bf16* p2; };

constexpr int GLDB = 48;
constexpr int GPLANE = 128 * GLDB;
constexpr int GSBUF = 4 * GPLANE;
constexpr int GSMEM = 2 * GSBUF;

__global__ void __launch_bounds__(128, 2)
gemm_mma_kernel(const bf16* __restrict__ Ah, PB3 BW,
                float* __restrict__ C, const float* __restrict__ R,
                int N, int K, size_t sCz, size_t aLoD, size_t bLoD) {
    extern __shared__ __align__(16) char smem[];
    const int tid = threadIdx.x;
    const int lane = tid & 31, wid = tid >> 5;
    const int wy = wid >> 1, wx = wid & 1;
    const u32 sbase = smem_u32(smem);

    const bf16* Bh = (blockIdx.z == 0) ? BW.p0 : (blockIdx.z == 1) ? BW.p1 : BW.p2;
    const bf16* Ab = Ah + (size_t)(blockIdx.y * 128) * K;
    const bf16* Bb = Bh + (size_t)(blockIdx.x * 128) * K;

    float acc[4][8][4];
#pragma unroll
    for (int i = 0; i < 4; i++)
#pragma unroll
        for (int j = 0; j < 8; j++)
#pragma unroll
            for (int q = 0; q < 4; q++) acc[i][j][q] = 0.f;

    const int nchunk = K >> 4;

    auto prefetch = [&](int c, int buf) {
        u32 sb = sbase + (u32)(buf * GSBUF);
        const bf16* Asrc = Ab + c * 16;
        const bf16* Bsrc = Bb + c * 16;
#pragma unroll
        for (int i = 0; i < 8; i++) {
            int idx = tid + i * 128;
            int plane = idx >> 8;
            int rem = idx & 255;
            int row = rem >> 1, hf = rem & 1;
            const bf16* src;
            if (plane == 0)      src = Asrc + (size_t)row * K + hf * 8;
            else if (plane == 1) src = Asrc + aLoD + (size_t)row * K + hf * 8;
            else if (plane == 2) src = Bsrc + (size_t)row * K + hf * 8;
            else                 src = Bsrc + bLoD + (size_t)row * K + hf * 8;
            cp16(sb + plane * GPLANE + row * GLDB + hf * 16, src);
        }
        cp_commit();
    };

    prefetch(0, 0);
    prefetch(1, 1);

    const int arow = wy * 64 + (lane & 15);
    const int acol = ((lane >> 4) & 1) * 16;
    const int brow0 = wx * 64 + (lane & 7);
    const int bcol = ((lane >> 3) & 1) * 16;

    for (int c = 0; c < nchunk; ++c) {
        if (c == nchunk - 1) cp_wait0(); else cp_wait1();
        __syncthreads();

        {
            u32 base = sbase + (u32)((c & 1) * GSBUF);
            u32 aH = base, aL = base + GPLANE;
            u32 bH = base + 2 * GPLANE, bL = base + 3 * GPLANE;

            u32 ah[4][4], al[4][4];
#pragma unroll
            for (int mt = 0; mt < 4; ++mt) {
                u32 off = (u32)((arow + mt * 16) * GLDB + acol);
                ldsm4(aH + off, ah[mt][0], ah[mt][1], ah[mt][2], ah[mt][3]);
                ldsm4(aL + off, al[mt][0], al[mt][1], al[mt][2], al[mt][3]);
            }
#pragma unroll
            for (int g = 0; g < 2; ++g) {
                u32 bh[4][2], bl[4][2];
#pragma unroll
                for (int nt = 0; nt < 4; ++nt) {
                    u32 off = (u32)((brow0 + (g * 4 + nt) * 8) * GLDB + bcol);
                    ldsm2(bH + off, bh[nt][0], bh[nt][1]);
                    ldsm2(bL + off, bl[nt][0], bl[nt][1]);
                }
#pragma unroll
                for (int mt = 0; mt < 4; ++mt)
#pragma unroll
                    for (int nt = 0; nt < 4; ++nt) {
                        float* a = acc[mt][g * 4 + nt];
                        mma16816(a, ah[mt][0], ah[mt][1], ah[mt][2], ah[mt][3],
                                 bh[nt][0], bh[nt][1]);
                        mma16816(a, ah[mt][0], ah[mt][1], ah[mt][2], ah[mt][3],
                                 bl[nt][0], bl[nt][1]);
                        mma16816(a, al[mt][0], al[mt][1], al[mt][2], al[mt][3],
                                 bh[nt][0], bh[nt][1]);
                    }
            }
        }
        __syncthreads();
        if (c + 2 < nchunk) prefetch(c + 2, c & 1);
    }

    float* Cz = C + (size_t)blockIdx.z * sCz;
    const float* Rz = R;
#pragma unroll
    for (int mt = 0; mt < 4; ++mt) {
        int row0 = blockIdx.y * 128 + wy * 64 + mt * 16 + (lane >> 2);
#pragma unroll
        for (int nt = 0; nt < 8; ++nt) {
            int col = blockIdx.x * 128 + wx * 64 + nt * 8 + (lane & 3) * 2;
            size_t o0 = (size_t)row0 * N + col;
            size_t o1 = (size_t)(row0 + 8) * N + col;
            float2 v0 = make_float2(acc[mt][nt][0], acc[mt][nt][1]);
            float2 v1 = make_float2(acc[mt][nt][2], acc[mt][nt][3]);
            if (Rz) {
                float2 r0 = *reinterpret_cast<const float2*>(Rz + o0);
                float2 r1 = *reinterpret_cast<const float2*>(Rz + o1);
                v0.x += r0.x; v0.y += r0.y;
                v1.x += r1.x; v1.y += r1.y;
            }
            *reinterpret_cast<float2*>(Cz + o0) = v0;
            *reinterpret_cast<float2*>(Cz + o1) = v1;
        }
    }
}

// ---------------- fused W1/W3 GEMM with swiglu epilogue (BK=16) ----------------
constexpr int WLDB  = 48;
constexpr int WAPL  = 128 * WLDB;
constexpr int WBPL  = 64 * WLDB;
constexpr int WSBUF = 2 * WAPL + 4 * WBPL;
constexpr int WSMEM = 2 * WSBUF;

__global__ void __launch_bounds__(128, 2)
gemm_w13_kernel(const bf16* __restrict__ Ah,
                const bf16* __restrict__ W1h, const bf16* __restrict__ W3h,
                bf16* __restrict__ gh, bf16* __restrict__ gl,
                int K, size_t aLoD, size_t bLoD) {
    extern __shared__ __align__(16) char smem[];
    const int tid = threadIdx.x;
    const int lane = tid & 31, wid = tid >> 5;
    const int wy = wid >> 1, wx = wid & 1;
    const u32 sbase = smem_u32(smem);

    const bf16* Ab = Ah + (size_t)(blockIdx.y * 128) * K;
    const bf16* B1 = W1h + (size_t)(blockIdx.x * 64) * K;
    const bf16* B3 = W3h + (size_t)(blockIdx.x * 64) * K;

    float acc1[4][4][4], acc3[4][4][4];
#pragma unroll
    for (int i = 0; i < 4; i++)
#pragma unroll
        for (int j = 0; j < 4; j++)
#pragma unroll
            for (int q = 0; q < 4; q++) { acc1[i][j][q] = 0.f; acc3[i][j][q] = 0.f; }

    const int nchunk = K >> 4;

    auto prefetch = [&](int c, int buf) {
        u32 sb = sbase + (u32)(buf * WSBUF);
        const bf16* Asrc = Ab + c * 16;
        const bf16* B1s = B1 + c * 16;
        const bf16* B3s = B3 + c * 16;
#pragma unroll
        for (int i = 0; i < 8; i++) {
            int idx = tid + i * 128;
            if (idx < 512) {
                int plane = idx >> 8;
                int rem = idx & 255;
                int row = rem >> 1, hf = rem & 1;
                const bf16* src = Asrc + (plane ? aLoD : 0) + (size_t)row * K + hf * 8;
                cp16(sb + plane * WAPL + row * WLDB + hf * 16, src);
            } else {
                int bidx = idx - 512;
                int plane = bidx >> 7;
                int rem = bidx & 127;
                int row = rem >> 1, hf = rem & 1;
                const bf16* src;
                if (plane == 0)      src = B1s + (size_t)row * K + hf * 8;
                else if (plane == 1) src = B1s + bLoD + (size_t)row * K + hf * 8;
                else if (plane == 2) src = B3s + (size_t)row * K + hf * 8;
                else                 src = B3s + bLoD + (size_t)row * K + hf * 8;
                cp16(sb + 2 * WAPL + plane * WBPL + row * WLDB + hf * 16, src);
            }
        }
        cp_commit();
    };

    prefetch(0, 0);
    prefetch(1, 1);

    const int arow = wy * 64 + (lane & 15);
    const int acol = ((lane >> 4) & 1) * 16;
    const int brow = wx * 32 + (lane & 7);
    const int bcol = ((lane >> 3) & 1) * 16;

    for (int c = 0; c < nchunk; ++c) {
        if (c == nchunk - 1) cp_wait0(); else cp_wait1();
        __syncthreads();

        {
            u32 base = sbase + (u32)((c & 1) * WSBUF);
            u32 aH = base, aL = base + WAPL;
            u32 b1H = base + 2 * WAPL;
            u32 b1L = b1H + WBPL;
            u32 b3H = b1L + WBPL;
            u32 b3L = b3H + WBPL;

            u32 ah[4][4], al[4][4];
#pragma unroll
            for (int mt = 0; mt < 4; ++mt) {
                u32 off = (u32)((arow + mt * 16) * WLDB + acol);
                ldsm4(aH + off, ah[mt][0], ah[mt][1], ah[mt][2], ah[mt][3]);
                ldsm4(aL + off, al[mt][0], al[mt][1], al[mt][2], al[mt][3]);
            }
            {
                u32 bh[4][2], bl[4][2];
#pragma unroll
                for (int nt = 0; nt < 4; ++nt) {
                    u32 off = (u32)((brow + nt * 8) * WLDB + bcol);
                    ldsm2(b1H + off, bh[nt][0], bh[nt][1]);
                    ldsm2(b1L + off, bl[nt][0], bl[nt][1]);
                }
#pragma unroll
                for (int mt = 0; mt < 4; ++mt)
#pragma unroll
                    for (int nt = 0; nt < 4; ++nt) {
                        float* a = acc1[mt][nt];
                        mma16816(a, ah[mt][0], ah[mt][1], ah[mt][2], ah[mt][3],
                                 bh[nt][0], bh[nt][1]);
                        mma16816(a, ah[mt][0], ah[mt][1], ah[mt][2], ah[mt][3],
                                 bl[nt][0], bl[nt][1]);
                        mma16816(a, al[mt][0], al[mt][1], al[mt][2], al[mt][3],
                                 bh[nt][0], bh[nt][1]);
                    }
            }
            {
                u32 bh[4][2], bl[4][2];
#pragma unroll
                for (int nt = 0; nt < 4; ++nt) {
                    u32 off = (u32)((brow + nt * 8) * WLDB + bcol);
                    ldsm2(b3H + off, bh[nt][0], bh[nt][1]);
                    ldsm2(b3L + off, bl[nt][0], bl[nt][1]);
                }
#pragma unroll
                for (int mt = 0; mt < 4; ++mt)
#pragma unroll
                    for (int nt = 0; nt < 4; ++nt) {
                        float* a = acc3[mt][nt];
                        mma16816(a, ah[mt][0], ah[mt][1], ah[mt][2], ah[mt][3],
                                 bh[nt][0], bh[nt][1]);
                        mma16816(a, ah[mt][0], ah[mt][1], ah[mt][2], ah[mt][3],
                                 bl[nt][0], bl[nt][1]);
                        mma16816(a, al[mt][0], al[mt][1], al[mt][2], al[mt][3],
                                 bh[nt][0], bh[nt][1]);
                    }
            }
        }
        __syncthreads();
        if (c + 2 < nchunk) prefetch(c + 2, c & 1);
    }

#pragma unroll
    for (int mt = 0; mt < 4; ++mt) {
        int row0 = blockIdx.y * 128 + wy * 64 + mt * 16 + (lane >> 2);
#pragma unroll
        for (int nt = 0; nt < 4; ++nt) {
            int col = blockIdx.x * 64 + wx * 32 + nt * 8 + (lane & 3) * 2;
            size_t o0 = (size_t)row0 * FFDIM + col;
            size_t o1 = (size_t)(row0 + 8) * FFDIM + col;
            float a0 = acc1[mt][nt][0], a1 = acc1[mt][nt][1];
            float a2 = acc1[mt][nt][2], a3 = acc1[mt][nt][3];
            float g0 = a0 / (1.0f + __expf(-a0)) * acc3[mt][nt][0];
            float g1 = a1 / (1.0f + __expf(-a1)) * acc3[mt][nt][1];
            float g2 = a2 / (1.0f + __expf(-a2)) * acc3[mt][nt][2];
            float g3 = a3 / (1.0f + __expf(-a3)) * acc3[mt][nt][3];
            u32 hi, lo;
            split2(g0, g1, hi, lo);
            *reinterpret_cast<u32*>(gh + o0) = hi;
            *reinterpret_cast<u32*>(gl + o0) = lo;
            split2(g2, g3, hi, lo);
            *reinterpret_cast<u32*>(gh + o1) = hi;
            *reinterpret_cast<u32*>(gl + o1) = lo;
        }
    }
}

// ---------------- host ----------------
extern "C" void kernel_launch(void* const* d_in, const int* in_sizes, int n_in,
                              void* d_out, int out_size) {
    const int*   tokens       = (const int*)d_in[0];
    const float* embed        = (const float*)d_in[1];
    const float* attn_norm_w  = (const float*)d_in[2];
    const float* wq           = (const float*)d_in[3];
    const float* wk           = (const float*)d_in[4];
    const float* wv           = (const float*)d_in[5];
    const float* wo           = (const float*)d_in[6];
    const float* ffn_norm_w   = (const float*)d_in[7];
    const float* w1           = (const float*)d_in[8];
    const float* w2           = (const float*)d_in[9];
    const float* w3           = (const float*)d_in[10];
    const float* final_norm_w = (const float*)d_in[11];
    float* out = (float*)d_out;

    cudaFuncSetAttribute(gemm_mma_kernel,
                         cudaFuncAttributeMaxDynamicSharedMemorySize, GSMEM);
    cudaFuncSetAttribute(gemm_w13_kernel,
                         cudaFuncAttributeMaxDynamicSharedMemorySize, WSMEM);
    cudaFuncSetAttribute(flash_kernel,
                         cudaFuncAttributeMaxDynamicSharedMemorySize, FLASH_SMEM);

    float* buf = nullptr;
    cudaGetSymbolAddress((void**)&buf, g_buf);
    int* seg = nullptr;
    cudaGetSymbolAddress((void**)&seg, g_seg);
    bf16* ab = nullptr;
    cudaGetSymbolAddress((void**)&ab, g_abuf);
    bf16* ws = nullptr;
    cudaGetSymbolAddress((void**)&ws, g_wsplit);

    float* x    = buf + OFF_X;
    float* y    = buf + OFF_Y;
    float* qr   = buf + OFF_Q;
    float* kr   = buf + OFF_K;
    float* vr   = buf + OFF_V;
    float* hf   = buf + OFF_HF;
    float* ssum = buf + OFF_SSUM;
    float* scnt = buf + OFF_SCNT;
    float* cosT = buf + OFF_COS;
    float* sinT = buf + OFF_SIN;

    bf16* xnh = ab + BXN;
    bf16* och = ab + BOC;
    bf16* qph = ab + BQP;
    bf16* kph = ab + BKP;
    bf16* vth = ab + BVT;
    bf16* ggh = ab + BGG;

    WSrc wsrc{{wq, wk, wv, wo, w1, w3, w2}};
    wsplit_all_kernel<<<(int)((TOT4 + 255) / 256), 256>>>(wsrc, ws);

    embed_kernel<<<BT, 128>>>(tokens, embed, x);
    rope_table_kernel<<<(SEQ * HALFHD + 255) / 256, 256>>>(cosT, sinT);

    for (int l = 0; l < NLAYER; l++) {
        const bf16* wqh = ws + WQO + (size_t)l * DIM * DIM;
        const bf16* wkh = ws + WKO + (size_t)l * DIM * DIM;
        const bf16* wvh = ws + WVO + (size_t)l * DIM * DIM;
        const bf16* woh = ws + WOO + (size_t)l * DIM * DIM;
        const bf16* w1h = ws + W1O + (size_t)l * FFDIM * DIM;
        const bf16* w3h = ws + W3O + (size_t)l * FFDIM * DIM;
        const bf16* w2h = ws + W2O + (size_t)l * DIM * FFDIM;

        rmsnorm_bf16_kernel<<<BT / 8, 256>>>(x, attn_norm_w + (size_t)l * DIM,
                                             xnh, xnh + NX);

        dim3 gqkv(DIM / 128, BT / 128, 3);
        gemm_mma_kernel<<<gqkv, 128, GSMEM>>>(xnh, PB3{wqh, wkh, wvh},
                                              qr, nullptr, DIM, DIM, NX, NX, NPROJ);

        prep_attn_kernel<<<PACK_BLOCKS + VT_BLOCKS, 256>>>(
            qr, kr, vr, cosT, sinT,
            qph, qph + NX, kph, kph + NX, vth, vth + NX);

        flash_kernel<<<dim3(SEQ / 128, BSZ * NHEAD), 256, FLASH_SMEM>>>(
            qph, qph + NX, kph, kph + NX, vth, vth + NX, och, och + NX);

        dim3 gproj(DIM / 128, BT / 128, 1);
        gemm_mma_kernel<<<gproj, 128, GSMEM>>>(och, PB3{woh, woh, woh},
                                               y, x, DIM, DIM, 0, NX, NPROJ);

        rmsnorm_bf16_kernel<<<BT / 8, 256>>>(y, ffn_norm_w + (size_t)l * DIM,
                                             xnh, xnh + NX);

        dim3 g13(FFDIM / 64, BT / 128, 1);
        gemm_w13_kernel<<<g13, 128, WSMEM>>>(xnh, w1h, w3h, ggh, ggh + NHID,
                                             DIM, NX, NFF);

        gemm_mma_kernel<<<gproj, 128, GSMEM>>>(ggh, PB3{w2h, w2h, w2h},
                                               x, y, DIM, FFDIM, 0, NHID, NFF);
    }

    rmsnorm_f32_kernel<<<BT / 8, 256>>>(x, final_norm_w, hf);

    segscan_kernel<<<BSZ, 256>>>(tokens, seg);
    zero_kernel<<<4096, 256>>>(ssum, NSEGS + NSEGC);
    segsum_kernel<<<BT, 128>>>(hf, seg, ssum, scnt);
    pool_kernel<<<BT, 128>>>(hf, seg, ssum, scnt, out);
}